// round 5
// baseline (speedup 1.0000x reference)
#include <cuda_runtime.h>

typedef unsigned long long u64;

// Problem constants
#define BB   8192
#define TT   80
#define HH   100
#define VV   100
#define G4   400
#define BCTA 56
#define ROWT 14      // ty groups (56/4) -- FAST index within warp
#define TXG  50      // tx groups (100/2 col-pairs)
#define NTHR 704     // 22 warps
#define NACT 700
#define NCTA 147

#define SMEM_L0 ((40000 + 5600) * 4 + 64 * 4)   // Whh0^T + h + tok
#define SMEM_GX ((40000 + 5600 + 400) * 4)      // Wih1^T + x + bias
#define SMEM_L1 ((40000 + 5600) * 4)            // Whh1^T + h

// ---------------- device scratch ----------------
__device__ float g_table0[VV * G4];                 // layer0 gate table (incl bias)
__device__ float g_Wt0 [HH * G4];                   // W_hh0^T [k][j]
__device__ float g_Wt1i[HH * G4];                   // W_ih1^T [k][j]
__device__ float g_Wt1h[HH * G4];                   // W_hh1^T [k][j]
__device__ float g_b1  [G4];
__device__ float g_h1[(size_t)TT * HH * BB + 64];   // layer0 out [t][k][b]
__device__ u64   g_gx[(size_t)TT * 200 * BB + 64];  // layer1 gate input, packed c-pairs [t][jp][b]
__device__ float g_h2[(size_t)HH * BB + 64];        // final h [k][b]

// ---------------- activations ----------------
__device__ __forceinline__ float sig_(float x) {
    return __fdividef(1.f, 1.f + __expf(-x));
}
__device__ __forceinline__ float tanh_(float x) {
    float e = __expf(2.f * x);
    return 1.f - __fdividef(2.f, e + 1.f);
}

// ---------------- packed f32x2 primitives ----------------
__device__ __forceinline__ void ffma2(u64& d, u64 a, u64 b) {
    asm("fma.rn.f32x2 %0, %1, %2, %0;" : "+l"(d) : "l"(a), "l"(b));
}
__device__ __forceinline__ u64 pack2(float lo, float hi) {
    u64 r; asm("mov.b64 %0, {%1, %2};" : "=l"(r) : "f"(lo), "f"(hi)); return r;
}
__device__ __forceinline__ float2 unpack2(u64 v) {
    float2 f; asm("mov.b64 {%0, %1}, %2;" : "=f"(f.x), "=f"(f.y) : "l"(v)); return f;
}

// ---------------- prep ----------------
__global__ void prep_kernel(const float* __restrict__ embed,
                            const float* __restrict__ Wih0,
                            const float* __restrict__ Whh0,
                            const float* __restrict__ bih0,
                            const float* __restrict__ bhh0,
                            const float* __restrict__ Wih1,
                            const float* __restrict__ Whh1,
                            const float* __restrict__ bih1,
                            const float* __restrict__ bhh1) {
    for (int idx = blockIdx.x * blockDim.x + threadIdx.x; idx < HH * G4;
         idx += gridDim.x * blockDim.x) {
        int k = idx / G4;
        int j = idx % G4;
        g_Wt0 [k * G4 + j] = Whh0[j * HH + k];
        g_Wt1i[k * G4 + j] = Wih1[j * HH + k];
        g_Wt1h[k * G4 + j] = Whh1[j * HH + k];
        float s = bih0[j] + bhh0[j];
        #pragma unroll
        for (int e = 0; e < 8; e++) s += Wih0[j * 8 + e] * embed[k * 8 + e];
        g_table0[k * G4 + j] = s;
        if (idx < G4) g_b1[idx] = bih1[idx] + bhh1[idx];
    }
}

// ---------------- packed register-blocked GEMM accumulate -------------------
// acc[g*4+r] (+)= W^T[k][g*100 + tx*2 .. +1] * in[k][b0 + ty*4 + r]
// 16 FFMA2 per k per thread; weights broadcast within warp (ty fast).
__device__ __forceinline__ void gemm_acc2(const float* __restrict__ ws,
                                          const float4* __restrict__ in4,
                                          int ty, int tx, u64 acc[16]) {
    const u64* wsu = (const u64*)ws;
    #pragma unroll 2
    for (int k = 0; k < HH; k++) {
        float4 h4 = in4[k * ROWT + ty];
        const u64* wr = wsu + k * 200 + tx;
        u64 wv0 = wr[0], wv1 = wr[50], wv2 = wr[100], wv3 = wr[150];
        u64 hp0 = pack2(h4.x, h4.x);
        u64 hp1 = pack2(h4.y, h4.y);
        u64 hp2 = pack2(h4.z, h4.z);
        u64 hp3 = pack2(h4.w, h4.w);
        ffma2(acc[0],  wv0, hp0); ffma2(acc[1],  wv0, hp1);
        ffma2(acc[2],  wv0, hp2); ffma2(acc[3],  wv0, hp3);
        ffma2(acc[4],  wv1, hp0); ffma2(acc[5],  wv1, hp1);
        ffma2(acc[6],  wv1, hp2); ffma2(acc[7],  wv1, hp3);
        ffma2(acc[8],  wv2, hp0); ffma2(acc[9],  wv2, hp1);
        ffma2(acc[10], wv2, hp2); ffma2(acc[11], wv2, hp3);
        ffma2(acc[12], wv3, hp0); ffma2(acc[13], wv3, hp1);
        ffma2(acc[14], wv3, hp2); ffma2(acc[15], wv3, hp3);
    }
}

// ---------------- LSTM cell elementwise + h store ---------------------------
__device__ __forceinline__ void cell_update2(u64 acc[16], float cst[4][2],
                                             float4* hs4, int ty, int tx) {
    float ho[4][2];
    #pragma unroll
    for (int r = 0; r < 4; r++) {
        float2 iv = unpack2(acc[0  + r]);
        float2 fv = unpack2(acc[4  + r]);
        float2 gv = unpack2(acc[8  + r]);
        float2 ov = unpack2(acc[12 + r]);
        {
            float i_ = sig_(iv.x), f_ = sig_(fv.x), g_ = tanh_(gv.x), o_ = sig_(ov.x);
            float cn = f_ * cst[r][0] + i_ * g_;
            cst[r][0] = cn;
            ho[r][0] = o_ * tanh_(cn);
        }
        {
            float i_ = sig_(iv.y), f_ = sig_(fv.y), g_ = tanh_(gv.y), o_ = sig_(ov.y);
            float cn = f_ * cst[r][1] + i_ * g_;
            cst[r][1] = cn;
            ho[r][1] = o_ * tanh_(cn);
        }
    }
    #pragma unroll
    for (int c = 0; c < 2; c++)
        hs4[(tx * 2 + c) * ROWT + ty] = make_float4(ho[0][c], ho[1][c], ho[2][c], ho[3][c]);
}

// ---------------- layer 0: sequential, table-driven input -------------------
__global__ void __launch_bounds__(NTHR, 1)
layer0_kernel(const int* __restrict__ x) {
    extern __shared__ float sm[];
    float* ws = sm;
    float* hs = sm + 40000;
    int*   tok = (int*)(sm + 45600);
    float4* hs4 = (float4*)hs;
    float4* gh14 = (float4*)g_h1;

    int tid = threadIdx.x, cta = blockIdx.x;
    int b0 = cta * BCTA;
    for (int i = tid; i < 10000; i += NTHR) ((float4*)ws)[i] = ((const float4*)g_Wt0)[i];
    for (int i = tid; i < 1400;  i += NTHR) hs4[i] = make_float4(0.f, 0.f, 0.f, 0.f);

    int ty = tid % ROWT, tx = tid / ROWT;   // ty FAST within warp (weight broadcast)
    bool act = tid < NACT;
    float cst[4][2] = {};
    u64 acc[16];

    for (int t = 0; t < TT; t++) {
        if (tid < BCTA) {
            int b = b0 + tid; if (b >= BB) b = BB - 1;
            tok[tid] = x[b * TT + t];
        }
        __syncthreads();
        if (act) {
            #pragma unroll
            for (int r = 0; r < 4; r++) {
                int tk = tok[ty * 4 + r];
                const u64* tp = (const u64*)g_table0 + tk * 200 + tx;
                acc[0  + r] = tp[0];
                acc[4  + r] = tp[50];
                acc[8  + r] = tp[100];
                acc[12 + r] = tp[150];
            }
            gemm_acc2(ws, hs4, ty, tx, acc);
        }
        __syncthreads();
        if (act) cell_update2(acc, cst, hs4, ty, tx);
        __syncthreads();
        int base = t * 204800 + cta * ROWT;
        for (int i = tid; i < 1400; i += NTHR) {
            int k = i / ROWT, bq = i % ROWT;
            if (b0 + bq * 4 + 3 < BB)
                gh14[base + k * 2048 + bq] = hs4[i];
        }
    }
}

// ---------------- gx: parallel W_ih1 GEMM over all t, weights resident ------
__global__ void __launch_bounds__(NTHR, 1)
gx_kernel() {
    extern __shared__ float sm[];
    float* ws = sm;
    float* xs = sm + 40000;
    float* b1s = sm + 45600;
    float4* xs4 = (float4*)xs;
    const float4* gh14 = (const float4*)g_h1;

    int tid = threadIdx.x, cta = blockIdx.x;
    int b0 = cta * BCTA;
    for (int i = tid; i < 10000; i += NTHR) ((float4*)ws)[i] = ((const float4*)g_Wt1i)[i];
    for (int i = tid; i < G4;    i += NTHR) b1s[i] = g_b1[i];

    int ty = tid % ROWT, tx = tid / ROWT;
    bool act = tid < NACT;
    bool strow = (b0 + ty * 4 + 3) < BB;
    u64 acc[16];

    for (int t = 0; t < TT; t++) {
        int base = t * 204800 + cta * ROWT;
        for (int i = tid; i < 1400; i += NTHR) {
            int k = i / ROWT, bq = i % ROWT;
            xs4[i] = gh14[base + k * 2048 + bq];
        }
        __syncthreads();
        if (act) {
            const u64* bp = (const u64*)b1s + tx;
            u64 bv0 = bp[0], bv1 = bp[50], bv2 = bp[100], bv3 = bp[150];
            #pragma unroll
            for (int r = 0; r < 4; r++) {
                acc[0 + r] = bv0; acc[4 + r] = bv1;
                acc[8 + r] = bv2; acc[12 + r] = bv3;
            }
            gemm_acc2(ws, xs4, ty, tx, acc);
            if (strow) {
                size_t tb = (size_t)t * 200 * BB;
                #pragma unroll
                for (int g = 0; g < 4; g++) {
                    int jp = g * 50 + tx;
                    u64* dst = g_gx + tb + (size_t)jp * BB + b0 + ty * 4;
                    ((ulonglong2*)dst)[0] = make_ulonglong2(acc[g * 4 + 0], acc[g * 4 + 1]);
                    ((ulonglong2*)dst)[1] = make_ulonglong2(acc[g * 4 + 2], acc[g * 4 + 3]);
                }
            }
        }
        __syncthreads();
    }
}

// ---------------- layer 1: sequential, W_hh1 resident ------------------------
__global__ void __launch_bounds__(NTHR, 1)
layer1_kernel() {
    extern __shared__ float sm[];
    float* ws = sm;
    float* hs = sm + 40000;
    float4* hs4 = (float4*)hs;

    int tid = threadIdx.x, cta = blockIdx.x;
    int b0 = cta * BCTA;
    for (int i = tid; i < 10000; i += NTHR) ((float4*)ws)[i] = ((const float4*)g_Wt1h)[i];
    for (int i = tid; i < 1400;  i += NTHR) hs4[i] = make_float4(0.f, 0.f, 0.f, 0.f);
    __syncthreads();

    int ty = tid % ROWT, tx = tid / ROWT;
    bool act = tid < NACT;
    float cst[4][2] = {};
    u64 acc[16];

    for (int t = 0; t < TT; t++) {
        if (act) {
            size_t tb = (size_t)t * 200 * BB;
            #pragma unroll
            for (int g = 0; g < 4; g++) {
                int jp = g * 50 + tx;
                const u64* src = g_gx + tb + (size_t)jp * BB + b0 + ty * 4;
                ulonglong2 q01 = ((const ulonglong2*)src)[0];
                ulonglong2 q23 = ((const ulonglong2*)src)[1];
                acc[g * 4 + 0] = q01.x; acc[g * 4 + 1] = q01.y;
                acc[g * 4 + 2] = q23.x; acc[g * 4 + 3] = q23.y;
            }
            gemm_acc2(ws, hs4, ty, tx, acc);
        }
        __syncthreads();
        if (act) cell_update2(acc, cst, hs4, ty, tx);
        __syncthreads();
    }
    for (int i = tid; i < 1400; i += NTHR) {
        int k = i / ROWT, bq = i % ROWT;
        if (b0 + bq * 4 + 3 < BB)
            ((float4*)g_h2)[k * 2048 + cta * ROWT + bq] = hs4[i];
    }
}

// ---------------- final FC ---------------------------------------------------
__global__ void __launch_bounds__(256, 1)
fc_kernel(const float* __restrict__ fcW, const float* __restrict__ fcb,
          float* __restrict__ out) {
    __shared__ float Ws[VV * HH];
    __shared__ float bs[VV];
    int tid = threadIdx.x;
    for (int i = tid; i < VV * HH; i += 256) Ws[i] = fcW[i];
    if (tid < VV) bs[tid] = fcb[tid];
    __syncthreads();

    int b = blockIdx.x * 256 + tid;
    float hr[HH];
    #pragma unroll
    for (int k = 0; k < HH; k++) hr[k] = g_h2[k * BB + b];

    const float4* Ws4 = (const float4*)Ws;
    float4* out4 = (float4*)out;
    #pragma unroll 1
    for (int v4 = 0; v4 < 25; v4++) {
        float a[4];
        #pragma unroll
        for (int q = 0; q < 4; q++) a[q] = bs[v4 * 4 + q];
        #pragma unroll
        for (int k4 = 0; k4 < 25; k4++) {
            #pragma unroll
            for (int q = 0; q < 4; q++) {
                float4 w = Ws4[(v4 * 4 + q) * 25 + k4];
                a[q] += hr[k4 * 4 + 0] * w.x + hr[k4 * 4 + 1] * w.y +
                        hr[k4 * 4 + 2] * w.z + hr[k4 * 4 + 3] * w.w;
            }
        }
        out4[b * 25 + v4] = make_float4(a[0], a[1], a[2], a[3]);
    }
}

// ---------------- launch ------------------------------------------------------
extern "C" void kernel_launch(void* const* d_in, const int* in_sizes, int n_in,
                              void* d_out, int out_size) {
    const int*   x     = (const int*)  d_in[0];
    const float* embed = (const float*)d_in[1];
    const float* Wih0  = (const float*)d_in[2];
    const float* Whh0  = (const float*)d_in[3];
    const float* bih0  = (const float*)d_in[4];
    const float* bhh0  = (const float*)d_in[5];
    const float* Wih1  = (const float*)d_in[6];
    const float* Whh1  = (const float*)d_in[7];
    const float* bih1  = (const float*)d_in[8];
    const float* bhh1  = (const float*)d_in[9];
    const float* fcW   = (const float*)d_in[10];
    const float* fcb   = (const float*)d_in[11];
    float* out = (float*)d_out;

    cudaFuncSetAttribute(layer0_kernel, cudaFuncAttributeMaxDynamicSharedMemorySize, SMEM_L0);
    cudaFuncSetAttribute(gx_kernel,     cudaFuncAttributeMaxDynamicSharedMemorySize, SMEM_GX);
    cudaFuncSetAttribute(layer1_kernel, cudaFuncAttributeMaxDynamicSharedMemorySize, SMEM_L1);

    prep_kernel<<<160, 256>>>(embed, Wih0, Whh0, bih0, bhh0, Wih1, Whh1, bih1, bhh1);
    layer0_kernel<<<NCTA, NTHR, SMEM_L0>>>(x);
    gx_kernel<<<NCTA, NTHR, SMEM_GX>>>();
    layer1_kernel<<<NCTA, NTHR, SMEM_L1>>>();
    fc_kernel<<<BB / 256, 256>>>(fcW, fcb, out);
}

// round 7
// speedup vs baseline: 1.1938x; 1.1938x over previous
#include <cuda_runtime.h>
#include <cuda_bf16.h>

typedef unsigned long long u64;
typedef unsigned int u32;

// Problem constants
#define BB   8192
#define TT   80
#define HH   100
#define VV   100
#define G4   400
#define BCTA 56
#define ROWG 7       // ty groups (56/8) -- FAST index within warp
#define NTHR 352
#define NACT 350
#define NCTA 147

#define SMEM_L0 ((40000 + 5600) * 4 + 256)
#define SMEM_L1 ((40000 + 5600) * 4)
#define SMEM_GX (179200 + 1600)

// ---------------- device scratch ----------------
__device__ float g_table0[VV * G4];                 // layer0 gate table (incl bias)
__device__ float g_Wt0 [HH * G4];                   // W_hh0^T [k][j]
__device__ float g_Wt1h[HH * G4];                   // W_hh1^T [k][j]
__device__ float g_b1  [G4];
__device__ __align__(16) u32 g_Bfrag[44800];        // W_ih1 bf16 frag images [kt][nt][lane][4]
__device__ u32  g_h1h[(size_t)TT * 56 * BB];        // h1 bf16-hi pairs [t][kp][b]
__device__ u32  g_h1l[(size_t)TT * 56 * BB];        // h1 bf16-lo pairs [t][kp][b]
__device__ u64  g_gx[(size_t)TT * 200 * BB + 64];   // layer1 gate input, packed pairs [t][jp][b]
__device__ float g_h2[(size_t)HH * BB + 64];        // final h [k][b]

// ---------------- activations ----------------
__device__ __forceinline__ float sig_(float x) {
    return __fdividef(1.f, 1.f + __expf(-x));
}
__device__ __forceinline__ float tanh_(float x) {
    float e = __expf(2.f * x);
    return 1.f - __fdividef(2.f, e + 1.f);
}

// ---------------- packed f32x2 ----------------
__device__ __forceinline__ void ffma2(u64& d, u64 a, u64 b) {
    asm("fma.rn.f32x2 %0, %1, %2, %0;" : "+l"(d) : "l"(a), "l"(b));
}
__device__ __forceinline__ u64 pack2(float lo, float hi) {
    u64 r; asm("mov.b64 %0, {%1, %2};" : "=l"(r) : "f"(lo), "f"(hi)); return r;
}
__device__ __forceinline__ float2 unpack2(u64 v) {
    float2 f; asm("mov.b64 {%0, %1}, %2;" : "=f"(f.x), "=f"(f.y) : "l"(v)); return f;
}
// bf16x2 pack: lo16 = lo_val, hi16 = hi_val
__device__ __forceinline__ u32 bfx2(float lo_val, float hi_val) {
    u32 r; asm("cvt.rn.bf16x2.f32 %0, %1, %2;" : "=r"(r) : "f"(hi_val), "f"(lo_val)); return r;
}
static __device__ __forceinline__ unsigned short bf16b(float f) {
    return __bfloat16_as_ushort(__float2bfloat16_rn(f));
}
static __device__ __forceinline__ float bf16f(unsigned short b) {
    return __uint_as_float((u32)b << 16);
}

// m16n8k16 bf16 MMA, D=f32 accumulate in place
#define MMA4(c, a, b0_, b1_) \
    asm volatile("mma.sync.aligned.m16n8k16.row.col.f32.bf16.bf16.f32 " \
        "{%0,%1,%2,%3},{%4,%5,%6,%7},{%8,%9},{%0,%1,%2,%3};" \
        : "+f"((c)[0]), "+f"((c)[1]), "+f"((c)[2]), "+f"((c)[3]) \
        : "r"((a)[0]), "r"((a)[1]), "r"((a)[2]), "r"((a)[3]), "r"(b0_), "r"(b1_))

// ---------------- prep ----------------
__global__ void prep_kernel(const float* __restrict__ embed,
                            const float* __restrict__ Wih0,
                            const float* __restrict__ Whh0,
                            const float* __restrict__ bih0,
                            const float* __restrict__ bhh0,
                            const float* __restrict__ Wih1,
                            const float* __restrict__ Whh1,
                            const float* __restrict__ bih1,
                            const float* __restrict__ bhh1) {
    int stride = gridDim.x * blockDim.x;
    int gid = blockIdx.x * blockDim.x + threadIdx.x;
    for (int idx = gid; idx < HH * G4; idx += stride) {
        int k = idx / G4;
        int j = idx % G4;
        g_Wt0 [k * G4 + j] = Whh0[j * HH + k];
        g_Wt1h[k * G4 + j] = Whh1[j * HH + k];
        float s = bih0[j] + bhh0[j];
        #pragma unroll
        for (int e = 0; e < 8; e++) s += Wih0[j * 8 + e] * embed[k * 8 + e];
        g_table0[k * G4 + j] = s;
        if (idx < G4) g_b1[idx] = bih1[idx] + bhh1[idx];
    }
    // B fragment images for mma.m16n8k16 (row.col): per (kt, nt, lane):
    //   b0 = {W[n][k0+2q], W[n][k0+2q+1]},  b1 = {W[n][k0+2q+8], W[n][k0+2q+9]}
    // with n = nt*8 + (lane>>2), k0 = kt*16, q = lane&3. hi and lo-residual images.
    for (int idx = gid; idx < 11200; idx += stride) {
        int kt = idx / 1600;
        int r  = idx % 1600;
        int nt = r / 32;
        int ln = r % 32;
        int gg = ln >> 2, qq = ln & 3;
        int n = nt * 8 + gg;
        float w[4];
        #pragma unroll
        for (int e = 0; e < 4; e++) {
            int k = kt * 16 + 2 * qq + (e & 1) + (e >> 1) * 8;
            w[e] = (k < HH) ? Wih1[n * HH + k] : 0.f;
        }
        unsigned short h[4];
        float res[4];
        #pragma unroll
        for (int e = 0; e < 4; e++) {
            h[e] = bf16b(w[e]);
            res[e] = w[e] - bf16f(h[e]);
        }
        g_Bfrag[idx * 4 + 0] = (u32)h[0] | ((u32)h[1] << 16);
        g_Bfrag[idx * 4 + 1] = (u32)h[2] | ((u32)h[3] << 16);
        g_Bfrag[idx * 4 + 2] = (u32)bf16b(res[0]) | ((u32)bf16b(res[1]) << 16);
        g_Bfrag[idx * 4 + 3] = (u32)bf16b(res[2]) | ((u32)bf16b(res[3]) << 16);
    }
}

// ---------------- scalar GEMM: r=8 rows x 1 col-pair x 4 gates --------------
__device__ __forceinline__ void gemm_acc8(const float* __restrict__ ws,
                                          const float4* __restrict__ in4,
                                          int ty, int tx, u64 acc[4][8]) {
    const u64* wsu = (const u64*)ws;
    #pragma unroll 2
    for (int k = 0; k < HH; k++) {
        float4 ha = in4[k * 14 + ty * 2];
        float4 hb = in4[k * 14 + ty * 2 + 1];
        const u64* wr = wsu + k * 200 + tx;
        u64 w0 = wr[0], w1 = wr[50], w2 = wr[100], w3 = wr[150];
        u64 hp[8];
        hp[0] = pack2(ha.x, ha.x); hp[1] = pack2(ha.y, ha.y);
        hp[2] = pack2(ha.z, ha.z); hp[3] = pack2(ha.w, ha.w);
        hp[4] = pack2(hb.x, hb.x); hp[5] = pack2(hb.y, hb.y);
        hp[6] = pack2(hb.z, hb.z); hp[7] = pack2(hb.w, hb.w);
        #pragma unroll
        for (int r = 0; r < 8; r++) {
            ffma2(acc[0][r], w0, hp[r]);
            ffma2(acc[1][r], w1, hp[r]);
            ffma2(acc[2][r], w2, hp[r]);
            ffma2(acc[3][r], w3, hp[r]);
        }
    }
}

__device__ __forceinline__ void cell_update8(u64 acc[4][8], float cst[8][2],
                                             float4* hs4, int ty, int tx) {
    float ho[8][2];
    #pragma unroll
    for (int r = 0; r < 8; r++) {
        float2 iv = unpack2(acc[0][r]);
        float2 fv = unpack2(acc[1][r]);
        float2 gv = unpack2(acc[2][r]);
        float2 ov = unpack2(acc[3][r]);
        {
            float i_ = sig_(iv.x), f_ = sig_(fv.x), g_ = tanh_(gv.x), o_ = sig_(ov.x);
            float cn = f_ * cst[r][0] + i_ * g_;
            cst[r][0] = cn; ho[r][0] = o_ * tanh_(cn);
        }
        {
            float i_ = sig_(iv.y), f_ = sig_(fv.y), g_ = tanh_(gv.y), o_ = sig_(ov.y);
            float cn = f_ * cst[r][1] + i_ * g_;
            cst[r][1] = cn; ho[r][1] = o_ * tanh_(cn);
        }
    }
    #pragma unroll
    for (int c = 0; c < 2; c++) {
        hs4[(tx * 2 + c) * 14 + ty * 2]     = make_float4(ho[0][c], ho[1][c], ho[2][c], ho[3][c]);
        hs4[(tx * 2 + c) * 14 + ty * 2 + 1] = make_float4(ho[4][c], ho[5][c], ho[6][c], ho[7][c]);
    }
}

// ---------------- layer 0 ----------------
__global__ void __launch_bounds__(NTHR, 1)
layer0_kernel(const int* __restrict__ x) {
    extern __shared__ float sm[];
    float* ws = sm;
    float* hs = sm + 40000;
    int*   tok = (int*)(sm + 45600);
    float4* hs4 = (float4*)hs;

    int tid = threadIdx.x, cta = blockIdx.x;
    int b0 = cta * BCTA;
    for (int i = tid; i < 10000; i += NTHR) ((float4*)ws)[i] = ((const float4*)g_Wt0)[i];
    for (int i = tid; i < 1400;  i += NTHR) hs4[i] = make_float4(0.f, 0.f, 0.f, 0.f);

    int ty = tid % ROWG, tx = tid / ROWG;   // ty fast within warp
    bool act = tid < NACT;
    float cst[8][2] = {};
    u64 acc[4][8];

    for (int t = 0; t < TT; t++) {
        if (tid < BCTA) {
            int b = b0 + tid; if (b >= BB) b = BB - 1;
            tok[tid] = x[b * TT + t];
        }
        __syncthreads();
        if (act) {
            #pragma unroll
            for (int r = 0; r < 8; r++) {
                int tk = tok[ty * 8 + r];
                const u64* tp = (const u64*)g_table0 + tk * 200 + tx;
                acc[0][r] = tp[0];
                acc[1][r] = tp[50];
                acc[2][r] = tp[100];
                acc[3][r] = tp[150];
            }
            gemm_acc8(ws, hs4, ty, tx, acc);
        }
        __syncthreads();
        if (act) cell_update8(acc, cst, hs4, ty, tx);
        __syncthreads();
        // write bf16 hi/lo pair images [t][kp][b], kp = k/2 (0..49), pad kp 50..55 = 0
        for (int i = tid; i < 784; i += NTHR) {
            if (i < 700) {
                int kp = i / 14, bq = i % 14;
                if (b0 + bq * 4 + 3 < BB) {
                    float4 fa = hs4[(2 * kp) * 14 + bq];
                    float4 fb = hs4[(2 * kp + 1) * 14 + bq];
                    uint4 hi, lo;
                    hi.x = bfx2(fa.x, fb.x); hi.y = bfx2(fa.y, fb.y);
                    hi.z = bfx2(fa.z, fb.z); hi.w = bfx2(fa.w, fb.w);
                    lo.x = bfx2(fa.x - __uint_as_float(hi.x << 16), fb.x - __uint_as_float(hi.x & 0xFFFF0000u));
                    lo.y = bfx2(fa.y - __uint_as_float(hi.y << 16), fb.y - __uint_as_float(hi.y & 0xFFFF0000u));
                    lo.z = bfx2(fa.z - __uint_as_float(hi.z << 16), fb.z - __uint_as_float(hi.z & 0xFFFF0000u));
                    lo.w = bfx2(fa.w - __uint_as_float(hi.w << 16), fb.w - __uint_as_float(hi.w & 0xFFFF0000u));
                    size_t idx4 = (size_t)(t * 56 + kp) * 2048 + cta * 14 + bq;
                    ((uint4*)g_h1h)[idx4] = hi;
                    ((uint4*)g_h1l)[idx4] = lo;
                }
            } else {
                int j = i - 700;
                int kp = 50 + j / 14, bq = j % 14;
                if (b0 + bq * 4 + 3 < BB) {
                    size_t idx4 = (size_t)(t * 56 + kp) * 2048 + cta * 14 + bq;
                    ((uint4*)g_h1h)[idx4] = make_uint4(0, 0, 0, 0);
                    ((uint4*)g_h1l)[idx4] = make_uint4(0, 0, 0, 0);
                }
            }
        }
    }
}

// ---------------- gx on legacy tensor cores (mma.sync bf16, 3-term split) ---
// D[b][j] = sum_k h1[t][k][b] * W_ih1[j][k] + bias[j]
__global__ void __launch_bounds__(256, 1)
gx_mma_kernel() {
    extern __shared__ char smx[];
    u32* Bs = (u32*)smx;                   // 44800 u32 fragment images
    float* bs = (float*)(smx + 179200);    // 400 bias
    int tid = threadIdx.x, wid = tid >> 5, lane = tid & 31;
    int g = lane >> 2, q = lane & 3;

    for (int i = tid; i < 11200; i += 256) ((uint4*)Bs)[i] = ((const uint4*)g_Bfrag)[i];
    for (int i = tid; i < G4; i += 256) bs[i] = g_b1[i];
    __syncthreads();
    const float2* bs2 = (const float2*)bs;
    const uint4* Bs4 = (const uint4*)Bs;

    for (int tile = blockIdx.x; tile < 2560; tile += 148) {
        int t = tile >> 5;
        int B0 = (tile & 31) << 8;
        u32 brow = (u32)(B0 + wid * 32 + g);
        u32 base = (u32)t * 458752u;       // t*56*8192
        u32 ah[7][2][4], al[7][2][4];
        #pragma unroll
        for (int kt = 0; kt < 7; kt++) {
            #pragma unroll
            for (int m = 0; m < 2; m++) {
                u32 i0 = base + (u32)(kt * 8 + q) * 8192u + brow + m * 16;
                u32 i2 = i0 + 4 * 8192u;
                ah[kt][m][0] = __ldg(g_h1h + i0);
                ah[kt][m][1] = __ldg(g_h1h + i0 + 8);
                ah[kt][m][2] = __ldg(g_h1h + i2);
                ah[kt][m][3] = __ldg(g_h1h + i2 + 8);
                al[kt][m][0] = __ldg(g_h1l + i0);
                al[kt][m][1] = __ldg(g_h1l + i0 + 8);
                al[kt][m][2] = __ldg(g_h1l + i2);
                al[kt][m][3] = __ldg(g_h1l + i2 + 8);
            }
        }
        size_t gxbase = (size_t)t * 1638400 + B0 + wid * 32 + g;
        #pragma unroll 1
        for (int nt = 0; nt < 50; nt++) {
            float c0[4] = {0.f, 0.f, 0.f, 0.f};
            float c1[4] = {0.f, 0.f, 0.f, 0.f};
            const uint4* bp = Bs4 + nt * 32 + lane;
            #pragma unroll
            for (int kt = 0; kt < 7; kt++) {
                uint4 bb = bp[kt * 1600];
                MMA4(c0, ah[kt][0], bb.x, bb.y);   // Ah*Bh
                MMA4(c0, ah[kt][0], bb.z, bb.w);   // Ah*Bl
                MMA4(c0, al[kt][0], bb.x, bb.y);   // Al*Bh
                MMA4(c1, ah[kt][1], bb.x, bb.y);
                MMA4(c1, ah[kt][1], bb.z, bb.w);
                MMA4(c1, al[kt][1], bb.x, bb.y);
            }
            float2 bv = bs2[nt * 4 + q];
            u64* dst = g_gx + gxbase + (size_t)(nt * 4 + q) * 8192;
            dst[0]  = pack2(c0[0] + bv.x, c0[1] + bv.y);
            dst[8]  = pack2(c0[2] + bv.x, c0[3] + bv.y);
            dst[16] = pack2(c1[0] + bv.x, c1[1] + bv.y);
            dst[24] = pack2(c1[2] + bv.x, c1[3] + bv.y);
        }
    }
}

// ---------------- layer 1 ----------------
__global__ void __launch_bounds__(NTHR, 1)
layer1_kernel() {
    extern __shared__ float sm[];
    float* ws = sm;
    float* hs = sm + 40000;
    float4* hs4 = (float4*)hs;

    int tid = threadIdx.x, cta = blockIdx.x;
    int b0 = cta * BCTA;
    for (int i = tid; i < 10000; i += NTHR) ((float4*)ws)[i] = ((const float4*)g_Wt1h)[i];
    for (int i = tid; i < 1400;  i += NTHR) hs4[i] = make_float4(0.f, 0.f, 0.f, 0.f);
    __syncthreads();

    int ty = tid % ROWG, tx = tid / ROWG;
    bool act = tid < NACT;
    float cst[8][2] = {};
    u64 acc[4][8];

    for (int t = 0; t < TT; t++) {
        if (act) {
            const u64* tb = g_gx + (size_t)t * 200 * BB + b0 + ty * 8;
            #pragma unroll
            for (int g = 0; g < 4; g++) {
                const ulonglong2* src = (const ulonglong2*)(tb + (size_t)(g * 50 + tx) * BB);
                ulonglong2 q0 = src[0], q1 = src[1], q2 = src[2], q3 = src[3];
                acc[g][0] = q0.x; acc[g][1] = q0.y;
                acc[g][2] = q1.x; acc[g][3] = q1.y;
                acc[g][4] = q2.x; acc[g][5] = q2.y;
                acc[g][6] = q3.x; acc[g][7] = q3.y;
            }
            gemm_acc8(ws, hs4, ty, tx, acc);
        }
        __syncthreads();
        if (act) cell_update8(acc, cst, hs4, ty, tx);
        __syncthreads();
    }
    for (int i = tid; i < 1400; i += NTHR) {
        int k = i / 14, bq = i % 14;
        if (b0 + bq * 4 + 3 < BB)
            ((float4*)g_h2)[k * 2048 + cta * 14 + bq] = hs4[i];
    }
}

// ---------------- final FC ----------------
__global__ void __launch_bounds__(256, 1)
fc_kernel(const float* __restrict__ fcW, const float* __restrict__ fcb,
          float* __restrict__ out) {
    __shared__ float Ws[VV * HH];
    __shared__ float bs[VV];
    int tid = threadIdx.x;
    for (int i = tid; i < VV * HH; i += 256) Ws[i] = fcW[i];
    if (tid < VV) bs[tid] = fcb[tid];
    __syncthreads();

    int b = blockIdx.x * 256 + tid;
    float hr[HH];
    #pragma unroll
    for (int k = 0; k < HH; k++) hr[k] = g_h2[k * BB + b];

    const float4* Ws4 = (const float4*)Ws;
    float4* out4 = (float4*)out;
    #pragma unroll 1
    for (int v4 = 0; v4 < 25; v4++) {
        float a[4];
        #pragma unroll
        for (int q = 0; q < 4; q++) a[q] = bs[v4 * 4 + q];
        #pragma unroll
        for (int k4 = 0; k4 < 25; k4++) {
            #pragma unroll
            for (int q = 0; q < 4; q++) {
                float4 w = Ws4[(v4 * 4 + q) * 25 + k4];
                a[q] += hr[k4 * 4 + 0] * w.x + hr[k4 * 4 + 1] * w.y +
                        hr[k4 * 4 + 2] * w.z + hr[k4 * 4 + 3] * w.w;
            }
        }
        out4[b * 25 + v4] = make_float4(a[0], a[1], a[2], a[3]);
    }
}

// ---------------- launch ----------------
extern "C" void kernel_launch(void* const* d_in, const int* in_sizes, int n_in,
                              void* d_out, int out_size) {
    const int*   x     = (const int*)  d_in[0];
    const float* embed = (const float*)d_in[1];
    const float* Wih0  = (const float*)d_in[2];
    const float* Whh0  = (const float*)d_in[3];
    const float* bih0  = (const float*)d_in[4];
    const float* bhh0  = (const float*)d_in[5];
    const float* Wih1  = (const float*)d_in[6];
    const float* Whh1  = (const float*)d_in[7];
    const float* bih1  = (const float*)d_in[8];
    const float* bhh1  = (const float*)d_in[9];
    const float* fcW   = (const float*)d_in[10];
    const float* fcb   = (const float*)d_in[11];
    float* out = (float*)d_out;

    cudaFuncSetAttribute(layer0_kernel, cudaFuncAttributeMaxDynamicSharedMemorySize, SMEM_L0);
    cudaFuncSetAttribute(gx_mma_kernel, cudaFuncAttributeMaxDynamicSharedMemorySize, SMEM_GX);
    cudaFuncSetAttribute(layer1_kernel, cudaFuncAttributeMaxDynamicSharedMemorySize, SMEM_L1);

    prep_kernel<<<160, 256>>>(embed, Wih0, Whh0, bih0, bhh0, Wih1, Whh1, bih1, bhh1);
    layer0_kernel<<<NCTA, NTHR, SMEM_L0>>>(x);
    gx_mma_kernel<<<148, 256, SMEM_GX>>>();
    layer1_kernel<<<NCTA, NTHR, SMEM_L1>>>();
    fc_kernel<<<BB / 256, 256>>>(fcW, fcb, out);
}

// round 8
// speedup vs baseline: 1.1966x; 1.0024x over previous
#include <cuda_runtime.h>
#include <cuda_bf16.h>

typedef unsigned long long u64;
typedef unsigned int u32;

// Problem constants
#define BB   8192
#define TT   80
#define HH   100
#define VV   100
#define G4   400
#define BCTA 56
#define ROWG 7       // ty groups (56/8) -- FAST index within warp
#define NTHR 352
#define NACT 350
#define NCTA 147

#define SMEM_L0 ((40000 + 5600) * 4 + 256)
#define SMEM_L1 ((40000 + 5600) * 4)
#define SMEM_GX (179200 + 1600)

// ---------------- device scratch ----------------
__device__ float g_table0[VV * G4];                 // layer0 gate table (incl bias)
__device__ float g_Wt0 [HH * G4];                   // W_hh0^T [k][j]
__device__ float g_Wt1h[HH * G4];                   // W_hh1^T [k][j]
__device__ float g_b1  [G4];
__device__ __align__(16) u32 g_Bfrag[44800];        // W_ih1 bf16 frag images [kt][nt][lane][4]
__device__ u32  g_h1h[(size_t)TT * 56 * BB];        // h1 bf16-hi pairs [t][kp][b]
__device__ u32  g_h1l[(size_t)TT * 56 * BB];        // h1 bf16-lo pairs [t][kp][b]
__device__ u64  g_gx[(size_t)TT * 200 * BB + 64];   // layer1 gate input, packed pairs [t][jp][b]
__device__ float g_h2[(size_t)HH * BB + 64];        // final h [k][b]

// ---------------- activations ----------------
__device__ __forceinline__ float sig_(float x) {
    return __fdividef(1.f, 1.f + __expf(-x));
}
__device__ __forceinline__ float tanh_(float x) {
    float e = __expf(2.f * x);
    return 1.f - __fdividef(2.f, e + 1.f);
}

// ---------------- packed f32x2 ----------------
__device__ __forceinline__ void ffma2(u64& d, u64 a, u64 b) {
    asm("fma.rn.f32x2 %0, %1, %2, %0;" : "+l"(d) : "l"(a), "l"(b));
}
__device__ __forceinline__ u64 pack2(float lo, float hi) {
    u64 r; asm("mov.b64 %0, {%1, %2};" : "=l"(r) : "f"(lo), "f"(hi)); return r;
}
__device__ __forceinline__ float2 unpack2(u64 v) {
    float2 f; asm("mov.b64 {%0, %1}, %2;" : "=f"(f.x), "=f"(f.y) : "l"(v)); return f;
}
// bf16x2 pack: lo16 = lo_val, hi16 = hi_val
__device__ __forceinline__ u32 bfx2(float lo_val, float hi_val) {
    u32 r; asm("cvt.rn.bf16x2.f32 %0, %1, %2;" : "=r"(r) : "f"(hi_val), "f"(lo_val)); return r;
}
static __device__ __forceinline__ unsigned short bf16b(float f) {
    return __bfloat16_as_ushort(__float2bfloat16_rn(f));
}
static __device__ __forceinline__ float bf16f(unsigned short b) {
    return __uint_as_float((u32)b << 16);
}

// m16n8k16 bf16 MMA, D=f32 accumulate in place
#define MMA4(c, a, b0_, b1_) \
    asm volatile("mma.sync.aligned.m16n8k16.row.col.f32.bf16.bf16.f32 " \
        "{%0,%1,%2,%3},{%4,%5,%6,%7},{%8,%9},{%0,%1,%2,%3};" \
        : "+f"((c)[0]), "+f"((c)[1]), "+f"((c)[2]), "+f"((c)[3]) \
        : "r"((a)[0]), "r"((a)[1]), "r"((a)[2]), "r"((a)[3]), "r"(b0_), "r"(b1_))

// ---------------- prep ----------------
__global__ void prep_kernel(const float* __restrict__ embed,
                            const float* __restrict__ Wih0,
                            const float* __restrict__ Whh0,
                            const float* __restrict__ bih0,
                            const float* __restrict__ bhh0,
                            const float* __restrict__ Wih1,
                            const float* __restrict__ Whh1,
                            const float* __restrict__ bih1,
                            const float* __restrict__ bhh1) {
    int stride = gridDim.x * blockDim.x;
    int gid = blockIdx.x * blockDim.x + threadIdx.x;
    for (int idx = gid; idx < HH * G4; idx += stride) {
        int k = idx / G4;
        int j = idx % G4;
        g_Wt0 [k * G4 + j] = Whh0[j * HH + k];
        g_Wt1h[k * G4 + j] = Whh1[j * HH + k];
        float s = bih0[j] + bhh0[j];
        #pragma unroll
        for (int e = 0; e < 8; e++) s += Wih0[j * 8 + e] * embed[k * 8 + e];
        g_table0[k * G4 + j] = s;
        if (idx < G4) g_b1[idx] = bih1[idx] + bhh1[idx];
    }
    // B fragment images for mma.m16n8k16 (row.col): per (kt, nt, lane):
    //   b0 = {W[n][k0+2q], W[n][k0+2q+1]},  b1 = {W[n][k0+2q+8], W[n][k0+2q+9]}
    // with n = nt*8 + (lane>>2), k0 = kt*16, q = lane&3. hi and lo-residual images.
    for (int idx = gid; idx < 11200; idx += stride) {
        int kt = idx / 1600;
        int r  = idx % 1600;
        int nt = r / 32;
        int ln = r % 32;
        int gg = ln >> 2, qq = ln & 3;
        int n = nt * 8 + gg;
        float w[4];
        #pragma unroll
        for (int e = 0; e < 4; e++) {
            int k = kt * 16 + 2 * qq + (e & 1) + (e >> 1) * 8;
            w[e] = (k < HH) ? Wih1[n * HH + k] : 0.f;
        }
        unsigned short h[4];
        float res[4];
        #pragma unroll
        for (int e = 0; e < 4; e++) {
            h[e] = bf16b(w[e]);
            res[e] = w[e] - bf16f(h[e]);
        }
        g_Bfrag[idx * 4 + 0] = (u32)h[0] | ((u32)h[1] << 16);
        g_Bfrag[idx * 4 + 1] = (u32)h[2] | ((u32)h[3] << 16);
        g_Bfrag[idx * 4 + 2] = (u32)bf16b(res[0]) | ((u32)bf16b(res[1]) << 16);
        g_Bfrag[idx * 4 + 3] = (u32)bf16b(res[2]) | ((u32)bf16b(res[3]) << 16);
    }
}

// ---------------- scalar GEMM: r=8 rows x 1 col-pair x 4 gates --------------
__device__ __forceinline__ void gemm_acc8(const float* __restrict__ ws,
                                          const float4* __restrict__ in4,
                                          int ty, int tx, u64 acc[4][8]) {
    const u64* wsu = (const u64*)ws;
    #pragma unroll 2
    for (int k = 0; k < HH; k++) {
        float4 ha = in4[k * 14 + ty * 2];
        float4 hb = in4[k * 14 + ty * 2 + 1];
        const u64* wr = wsu + k * 200 + tx;
        u64 w0 = wr[0], w1 = wr[50], w2 = wr[100], w3 = wr[150];
        u64 hp[8];
        hp[0] = pack2(ha.x, ha.x); hp[1] = pack2(ha.y, ha.y);
        hp[2] = pack2(ha.z, ha.z); hp[3] = pack2(ha.w, ha.w);
        hp[4] = pack2(hb.x, hb.x); hp[5] = pack2(hb.y, hb.y);
        hp[6] = pack2(hb.z, hb.z); hp[7] = pack2(hb.w, hb.w);
        #pragma unroll
        for (int r = 0; r < 8; r++) {
            ffma2(acc[0][r], w0, hp[r]);
            ffma2(acc[1][r], w1, hp[r]);
            ffma2(acc[2][r], w2, hp[r]);
            ffma2(acc[3][r], w3, hp[r]);
        }
    }
}

__device__ __forceinline__ void cell_update8(u64 acc[4][8], float cst[8][2],
                                             float4* hs4, int ty, int tx) {
    float ho[8][2];
    #pragma unroll
    for (int r = 0; r < 8; r++) {
        float2 iv = unpack2(acc[0][r]);
        float2 fv = unpack2(acc[1][r]);
        float2 gv = unpack2(acc[2][r]);
        float2 ov = unpack2(acc[3][r]);
        {
            float i_ = sig_(iv.x), f_ = sig_(fv.x), g_ = tanh_(gv.x), o_ = sig_(ov.x);
            float cn = f_ * cst[r][0] + i_ * g_;
            cst[r][0] = cn; ho[r][0] = o_ * tanh_(cn);
        }
        {
            float i_ = sig_(iv.y), f_ = sig_(fv.y), g_ = tanh_(gv.y), o_ = sig_(ov.y);
            float cn = f_ * cst[r][1] + i_ * g_;
            cst[r][1] = cn; ho[r][1] = o_ * tanh_(cn);
        }
    }
    #pragma unroll
    for (int c = 0; c < 2; c++) {
        hs4[(tx * 2 + c) * 14 + ty * 2]     = make_float4(ho[0][c], ho[1][c], ho[2][c], ho[3][c]);
        hs4[(tx * 2 + c) * 14 + ty * 2 + 1] = make_float4(ho[4][c], ho[5][c], ho[6][c], ho[7][c]);
    }
}

// ---------------- layer 0 ----------------
__global__ void __launch_bounds__(NTHR, 1)
layer0_kernel(const int* __restrict__ x) {
    extern __shared__ float sm[];
    float* ws = sm;
    float* hs = sm + 40000;
    int*   tok = (int*)(sm + 45600);
    float4* hs4 = (float4*)hs;

    int tid = threadIdx.x, cta = blockIdx.x;
    int b0 = cta * BCTA;
    for (int i = tid; i < 10000; i += NTHR) ((float4*)ws)[i] = ((const float4*)g_Wt0)[i];
    for (int i = tid; i < 1400;  i += NTHR) hs4[i] = make_float4(0.f, 0.f, 0.f, 0.f);

    int ty = tid % ROWG, tx = tid / ROWG;   // ty fast within warp
    bool act = tid < NACT;
    float cst[8][2] = {};
    u64 acc[4][8];

    for (int t = 0; t < TT; t++) {
        if (tid < BCTA) {
            int b = b0 + tid; if (b >= BB) b = BB - 1;
            tok[tid] = x[b * TT + t];
        }
        __syncthreads();
        if (act) {
            #pragma unroll
            for (int r = 0; r < 8; r++) {
                int tk = tok[ty * 8 + r];
                const u64* tp = (const u64*)g_table0 + tk * 200 + tx;
                acc[0][r] = tp[0];
                acc[1][r] = tp[50];
                acc[2][r] = tp[100];
                acc[3][r] = tp[150];
            }
            gemm_acc8(ws, hs4, ty, tx, acc);
        }
        __syncthreads();
        if (act) cell_update8(acc, cst, hs4, ty, tx);
        __syncthreads();
        // write bf16 hi/lo pair images [t][kp][b], kp = k/2 (0..49), pad kp 50..55 = 0
        for (int i = tid; i < 784; i += NTHR) {
            if (i < 700) {
                int kp = i / 14, bq = i % 14;
                if (b0 + bq * 4 + 3 < BB) {
                    float4 fa = hs4[(2 * kp) * 14 + bq];
                    float4 fb = hs4[(2 * kp + 1) * 14 + bq];
                    uint4 hi, lo;
                    hi.x = bfx2(fa.x, fb.x); hi.y = bfx2(fa.y, fb.y);
                    hi.z = bfx2(fa.z, fb.z); hi.w = bfx2(fa.w, fb.w);
                    lo.x = bfx2(fa.x - __uint_as_float(hi.x << 16), fb.x - __uint_as_float(hi.x & 0xFFFF0000u));
                    lo.y = bfx2(fa.y - __uint_as_float(hi.y << 16), fb.y - __uint_as_float(hi.y & 0xFFFF0000u));
                    lo.z = bfx2(fa.z - __uint_as_float(hi.z << 16), fb.z - __uint_as_float(hi.z & 0xFFFF0000u));
                    lo.w = bfx2(fa.w - __uint_as_float(hi.w << 16), fb.w - __uint_as_float(hi.w & 0xFFFF0000u));
                    size_t idx4 = (size_t)(t * 56 + kp) * 2048 + cta * 14 + bq;
                    ((uint4*)g_h1h)[idx4] = hi;
                    ((uint4*)g_h1l)[idx4] = lo;
                }
            } else {
                int j = i - 700;
                int kp = 50 + j / 14, bq = j % 14;
                if (b0 + bq * 4 + 3 < BB) {
                    size_t idx4 = (size_t)(t * 56 + kp) * 2048 + cta * 14 + bq;
                    ((uint4*)g_h1h)[idx4] = make_uint4(0, 0, 0, 0);
                    ((uint4*)g_h1l)[idx4] = make_uint4(0, 0, 0, 0);
                }
            }
        }
    }
}

// ---------------- gx on legacy tensor cores (mma.sync bf16, 3-term split) ---
// D[b][j] = sum_k h1[t][k][b] * W_ih1[j][k] + bias[j]
__global__ void __launch_bounds__(256, 1)
gx_mma_kernel() {
    extern __shared__ char smx[];
    u32* Bs = (u32*)smx;                   // 44800 u32 fragment images
    float* bs = (float*)(smx + 179200);    // 400 bias
    int tid = threadIdx.x, wid = tid >> 5, lane = tid & 31;
    int g = lane >> 2, q = lane & 3;

    for (int i = tid; i < 11200; i += 256) ((uint4*)Bs)[i] = ((const uint4*)g_Bfrag)[i];
    for (int i = tid; i < G4; i += 256) bs[i] = g_b1[i];
    __syncthreads();
    const float2* bs2 = (const float2*)bs;
    const uint4* Bs4 = (const uint4*)Bs;

    for (int tile = blockIdx.x; tile < 2560; tile += 148) {
        int t = tile >> 5;
        int B0 = (tile & 31) << 8;
        u32 brow = (u32)(B0 + wid * 32 + g);
        u32 base = (u32)t * 458752u;       // t*56*8192
        u32 ah[7][2][4], al[7][2][4];
        #pragma unroll
        for (int kt = 0; kt < 7; kt++) {
            #pragma unroll
            for (int m = 0; m < 2; m++) {
                u32 i0 = base + (u32)(kt * 8 + q) * 8192u + brow + m * 16;
                u32 i2 = i0 + 4 * 8192u;
                ah[kt][m][0] = __ldg(g_h1h + i0);
                ah[kt][m][1] = __ldg(g_h1h + i0 + 8);
                ah[kt][m][2] = __ldg(g_h1h + i2);
                ah[kt][m][3] = __ldg(g_h1h + i2 + 8);
                al[kt][m][0] = __ldg(g_h1l + i0);
                al[kt][m][1] = __ldg(g_h1l + i0 + 8);
                al[kt][m][2] = __ldg(g_h1l + i2);
                al[kt][m][3] = __ldg(g_h1l + i2 + 8);
            }
        }
        size_t gxbase = (size_t)t * 1638400 + B0 + wid * 32 + g;
        #pragma unroll 1
        for (int nt = 0; nt < 50; nt++) {
            float c0[4] = {0.f, 0.f, 0.f, 0.f};
            float c1[4] = {0.f, 0.f, 0.f, 0.f};
            const uint4* bp = Bs4 + nt * 32 + lane;
            #pragma unroll
            for (int kt = 0; kt < 7; kt++) {
                uint4 bb = bp[kt * 1600];
                MMA4(c0, ah[kt][0], bb.x, bb.y);   // Ah*Bh
                MMA4(c0, ah[kt][0], bb.z, bb.w);   // Ah*Bl
                MMA4(c0, al[kt][0], bb.x, bb.y);   // Al*Bh
                MMA4(c1, ah[kt][1], bb.x, bb.y);
                MMA4(c1, ah[kt][1], bb.z, bb.w);
                MMA4(c1, al[kt][1], bb.x, bb.y);
            }
            float2 bv = bs2[nt * 4 + q];
            u64* dst = g_gx + gxbase + (size_t)(nt * 4 + q) * 8192;
            dst[0]  = pack2(c0[0] + bv.x, c0[1] + bv.y);
            dst[8]  = pack2(c0[2] + bv.x, c0[3] + bv.y);
            dst[16] = pack2(c1[0] + bv.x, c1[1] + bv.y);
            dst[24] = pack2(c1[2] + bv.x, c1[3] + bv.y);
        }
    }
}

// ---------------- layer 1 ----------------
__global__ void __launch_bounds__(NTHR, 1)
layer1_kernel() {
    extern __shared__ float sm[];
    float* ws = sm;
    float* hs = sm + 40000;
    float4* hs4 = (float4*)hs;

    int tid = threadIdx.x, cta = blockIdx.x;
    int b0 = cta * BCTA;
    for (int i = tid; i < 10000; i += NTHR) ((float4*)ws)[i] = ((const float4*)g_Wt1h)[i];
    for (int i = tid; i < 1400;  i += NTHR) hs4[i] = make_float4(0.f, 0.f, 0.f, 0.f);
    __syncthreads();

    int ty = tid % ROWG, tx = tid / ROWG;
    bool act = tid < NACT;
    float cst[8][2] = {};
    u64 acc[4][8];

    for (int t = 0; t < TT; t++) {
        if (act) {
            const u64* tb = g_gx + (size_t)t * 200 * BB + b0 + ty * 8;
            #pragma unroll
            for (int g = 0; g < 4; g++) {
                const ulonglong2* src = (const ulonglong2*)(tb + (size_t)(g * 50 + tx) * BB);
                ulonglong2 q0 = src[0], q1 = src[1], q2 = src[2], q3 = src[3];
                acc[g][0] = q0.x; acc[g][1] = q0.y;
                acc[g][2] = q1.x; acc[g][3] = q1.y;
                acc[g][4] = q2.x; acc[g][5] = q2.y;
                acc[g][6] = q3.x; acc[g][7] = q3.y;
            }
            gemm_acc8(ws, hs4, ty, tx, acc);
        }
        __syncthreads();
        if (act) cell_update8(acc, cst, hs4, ty, tx);
        __syncthreads();
    }
    for (int i = tid; i < 1400; i += NTHR) {
        int k = i / 14, bq = i % 14;
        if (b0 + bq * 4 + 3 < BB)
            ((float4*)g_h2)[k * 2048 + cta * 14 + bq] = hs4[i];
    }
}

// ---------------- final FC ----------------
__global__ void __launch_bounds__(256, 1)
fc_kernel(const float* __restrict__ fcW, const float* __restrict__ fcb,
          float* __restrict__ out) {
    __shared__ float Ws[VV * HH];
    __shared__ float bs[VV];
    int tid = threadIdx.x;
    for (int i = tid; i < VV * HH; i += 256) Ws[i] = fcW[i];
    if (tid < VV) bs[tid] = fcb[tid];
    __syncthreads();

    int b = blockIdx.x * 256 + tid;
    float hr[HH];
    #pragma unroll
    for (int k = 0; k < HH; k++) hr[k] = g_h2[k * BB + b];

    const float4* Ws4 = (const float4*)Ws;
    float4* out4 = (float4*)out;
    #pragma unroll 1
    for (int v4 = 0; v4 < 25; v4++) {
        float a[4];
        #pragma unroll
        for (int q = 0; q < 4; q++) a[q] = bs[v4 * 4 + q];
        #pragma unroll
        for (int k4 = 0; k4 < 25; k4++) {
            #pragma unroll
            for (int q = 0; q < 4; q++) {
                float4 w = Ws4[(v4 * 4 + q) * 25 + k4];
                a[q] += hr[k4 * 4 + 0] * w.x + hr[k4 * 4 + 1] * w.y +
                        hr[k4 * 4 + 2] * w.z + hr[k4 * 4 + 3] * w.w;
            }
        }
        out4[b * 25 + v4] = make_float4(a[0], a[1], a[2], a[3]);
    }
}

// ---------------- launch ----------------
extern "C" void kernel_launch(void* const* d_in, const int* in_sizes, int n_in,
                              void* d_out, int out_size) {
    const int*   x     = (const int*)  d_in[0];
    const float* embed = (const float*)d_in[1];
    const float* Wih0  = (const float*)d_in[2];
    const float* Whh0  = (const float*)d_in[3];
    const float* bih0  = (const float*)d_in[4];
    const float* bhh0  = (const float*)d_in[5];
    const float* Wih1  = (const float*)d_in[6];
    const float* Whh1  = (const float*)d_in[7];
    const float* bih1  = (const float*)d_in[8];
    const float* bhh1  = (const float*)d_in[9];
    const float* fcW   = (const float*)d_in[10];
    const float* fcb   = (const float*)d_in[11];
    float* out = (float*)d_out;

    cudaFuncSetAttribute(layer0_kernel, cudaFuncAttributeMaxDynamicSharedMemorySize, SMEM_L0);
    cudaFuncSetAttribute(gx_mma_kernel, cudaFuncAttributeMaxDynamicSharedMemorySize, SMEM_GX);
    cudaFuncSetAttribute(layer1_kernel, cudaFuncAttributeMaxDynamicSharedMemorySize, SMEM_L1);

    prep_kernel<<<160, 256>>>(embed, Wih0, Whh0, bih0, bhh0, Wih1, Whh1, bih1, bhh1);
    layer0_kernel<<<NCTA, NTHR, SMEM_L0>>>(x);
    gx_mma_kernel<<<148, 256, SMEM_GX>>>();
    layer1_kernel<<<NCTA, NTHR, SMEM_L1>>>();
    fc_kernel<<<BB / 256, 256>>>(fcW, fcb, out);
}

// round 9
// speedup vs baseline: 1.7630x; 1.4733x over previous
#include <cuda_runtime.h>
#include <cuda_bf16.h>

typedef unsigned long long u64;
typedef unsigned int u32;
typedef unsigned short u16;

#define BB 8192
#define TT 80
#define HH 100
#define VV 100

#define IMG   20800           // u32 per B term-image (50 nt * 416)
#define NTBLK 416             // u32 per n-tile block
#define A_OFF   41600         // smem u32 offsets
#define AL_OFF  44928
#define TOK_OFF 48256
#define SMEM_REC (48320 * 4)
#define SMEM_GX  (42000 * 4)

// ---------------- device scratch ----------------
__device__ __align__(16) u32 g_Bf_hh0[41600];           // W_hh0 frag images (hi, lo)
__device__ __align__(16) u32 g_Bf_hh1[41600];           // W_hh1
__device__ __align__(16) u32 g_Bf_ih1[41600];           // W_ih1
__device__ __align__(16) float4 g_tab0[VV * HH];        // layer0 table, n'-grouped per h
__device__ __align__(16) float4 g_b1f4[HH];             // layer1 bias per h
__device__ __align__(16) u32 g_h1f[(size_t)TT * 128 * 6656];  // h1 A-images [t*128+cta][hi|lo][64][52]
__device__ __align__(16) float4 g_gx[(size_t)TT * BB * HH];   // layer1 gate inputs per (t,b,h)
__device__ float g_h2[HH * BB];                         // final h [k][b]

// ---------------- helpers ----------------
__device__ __forceinline__ float sig_(float x) {
    return __fdividef(1.f, 1.f + __expf(-x));
}
__device__ __forceinline__ float tanh_(float x) {
    float e = __expf(2.f * x);
    return 1.f - __fdividef(2.f, e + 1.f);
}
static __device__ __forceinline__ u16 bf16b(float f) {
    return __bfloat16_as_ushort(__float2bfloat16_rn(f));
}
static __device__ __forceinline__ float bf16f(u16 b) {
    return __uint_as_float((u32)b << 16);
}

#define MMA16(c, a, b0_, b1_) \
    asm volatile("mma.sync.aligned.m16n8k16.row.col.f32.bf16.bf16.f32 " \
        "{%0,%1,%2,%3},{%4,%5,%6,%7},{%8,%9},{%0,%1,%2,%3};" \
        : "+f"((c)[0]), "+f"((c)[1]), "+f"((c)[2]), "+f"((c)[3]) \
        : "r"((a)[0]), "r"((a)[1]), "r"((a)[2]), "r"((a)[3]), "r"(b0_), "r"(b1_))

#define MMA8(c, a0_, a1_, b0_) \
    asm volatile("mma.sync.aligned.m16n8k8.row.col.f32.bf16.bf16.f32 " \
        "{%0,%1,%2,%3},{%4,%5},{%6},{%0,%1,%2,%3};" \
        : "+f"((c)[0]), "+f"((c)[1]), "+f"((c)[2]), "+f"((c)[3]) \
        : "r"(a0_), "r"(a1_), "r"(b0_))

// A fragments from a [64 rows][52 k-pairs] u32 pair-image
__device__ __forceinline__ void load_afrags(const u32* Ah, const u32* Al,
                                            int m, int lane, u32 ahi[26], u32 alo[26]) {
    int g = lane >> 2, q = lane & 3;
    int r0 = (m * 16 + g) * 52, r8 = r0 + 8 * 52;
    #pragma unroll
    for (int kt = 0; kt < 6; kt++) {
        int kp = kt * 8 + q;
        ahi[kt * 4 + 0] = Ah[r0 + kp];     ahi[kt * 4 + 1] = Ah[r8 + kp];
        ahi[kt * 4 + 2] = Ah[r0 + kp + 4]; ahi[kt * 4 + 3] = Ah[r8 + kp + 4];
        alo[kt * 4 + 0] = Al[r0 + kp];     alo[kt * 4 + 1] = Al[r8 + kp];
        alo[kt * 4 + 2] = Al[r0 + kp + 4]; alo[kt * 4 + 3] = Al[r8 + kp + 4];
    }
    ahi[24] = Ah[r0 + 48 + q]; ahi[25] = Ah[r8 + 48 + q];
    alo[24] = Al[r0 + 48 + q]; alo[25] = Al[r8 + 48 + q];
}

// One n8 tile x K=104, 3-term split on 3 independent accumulator chains
__device__ __forceinline__ void mma_tile(float c[4], const u32 ahi[26], const u32 alo[26],
                                         const u32* Bh, const u32* Bl, int lane) {
    float cA[4] = {0.f, 0.f, 0.f, 0.f};
    float cB[4] = {0.f, 0.f, 0.f, 0.f};
    float cC[4] = {0.f, 0.f, 0.f, 0.f};
    #pragma unroll
    for (int kt = 0; kt < 6; kt++) {
        u64 bh = *(const u64*)(Bh + kt * 64 + lane * 2);
        u64 bl = *(const u64*)(Bl + kt * 64 + lane * 2);
        u32 bh0 = (u32)bh, bh1 = (u32)(bh >> 32);
        u32 bl0 = (u32)bl, bl1 = (u32)(bl >> 32);
        MMA16(cA, ahi + kt * 4, bh0, bh1);
        MMA16(cB, ahi + kt * 4, bl0, bl1);
        MMA16(cC, alo + kt * 4, bh0, bh1);
    }
    u32 bh8 = Bh[384 + lane], bl8 = Bl[384 + lane];
    MMA8(cA, ahi[24], ahi[25], bh8);
    MMA8(cB, ahi[24], ahi[25], bl8);
    MMA8(cC, alo[24], alo[25], bh8);
    #pragma unroll
    for (int i = 0; i < 4; i++) c[i] = (cA[i] + cB[i]) + cC[i];
}

// ---------------- prep ----------------
__global__ void prep_kernel(const float* __restrict__ embed,
                            const float* __restrict__ Wih0,
                            const float* __restrict__ Whh0,
                            const float* __restrict__ bih0,
                            const float* __restrict__ bhh0,
                            const float* __restrict__ Wih1,
                            const float* __restrict__ Whh1,
                            const float* __restrict__ bih1,
                            const float* __restrict__ bhh1) {
    int stride = gridDim.x * blockDim.x;
    int gid = blockIdx.x * blockDim.x + threadIdx.x;

    // B fragment images, n' = 4h+gate ordering, j(n') = (n'&3)*100 + (n'>>2)
    for (int idx = gid; idx < 3 * 41600; idx += stride) {
        int sel = idx / 41600;
        int r = idx % 41600;
        const float* W = sel == 0 ? Whh0 : (sel == 1 ? Whh1 : Wih1);
        u32* dst = sel == 0 ? g_Bf_hh0 : (sel == 1 ? g_Bf_hh1 : g_Bf_ih1);
        int img = r / IMG;
        int r2 = r % IMG;
        int nt = r2 / NTBLK, o = r2 % NTBLK;
        int lane, kb;
        if (o < 384) {
            int kt = o >> 6; int w = o & 63;
            lane = w >> 1;
            kb = kt * 16 + 2 * (lane & 3) + (w & 1) * 8;
        } else {
            lane = o - 384;
            kb = 96 + 2 * (lane & 3);
        }
        int np = nt * 8 + (lane >> 2);
        int j = (np & 3) * 100 + (np >> 2);
        float w0 = (kb < HH) ? W[j * HH + kb] : 0.f;
        float w1 = (kb + 1 < HH) ? W[j * HH + kb + 1] : 0.f;
        u32 v;
        if (img == 0) {
            v = (u32)bf16b(w0) | ((u32)bf16b(w1) << 16);
        } else {
            float q0 = w0 - bf16f(bf16b(w0));
            float q1 = w1 - bf16f(bf16b(w1));
            v = (u32)bf16b(q0) | ((u32)bf16b(q1) << 16);
        }
        dst[r] = v;
    }
    // layer0 table: per (v,h) the 4 gate values of W_ih0*emb[v] + biases
    for (int idx = gid; idx < VV * HH; idx += stride) {
        int v = idx / HH, h = idx % HH;
        float tv[4];
        #pragma unroll
        for (int gt = 0; gt < 4; gt++) {
            int j = gt * HH + h;
            float s = bih0[j] + bhh0[j];
            #pragma unroll
            for (int e = 0; e < 8; e++) s += Wih0[j * 8 + e] * embed[v * 8 + e];
            tv[gt] = s;
        }
        g_tab0[idx] = make_float4(tv[0], tv[1], tv[2], tv[3]);
    }
    // layer1 bias per h
    for (int idx = gid; idx < HH; idx += stride) {
        g_b1f4[idx] = make_float4(bih1[idx] + bhh1[idx],
                                  bih1[HH + idx] + bhh1[HH + idx],
                                  bih1[2 * HH + idx] + bhh1[2 * HH + idx],
                                  bih1[3 * HH + idx] + bhh1[3 * HH + idx]);
    }
}

// ---------------- recurrent layer (L=0: layer0, L=1: layer1) ----------------
template <int L>
__global__ void __launch_bounds__(256, 1) rec_kernel(const int* __restrict__ x) {
    extern __shared__ u32 sm[];
    u32* Bh = sm;
    u32* Bl = sm + IMG;
    u32* Ah = sm + A_OFF;
    u32* Al = sm + AL_OFF;
    int* tok = (int*)(sm + TOK_OFF);

    int tid = threadIdx.x, cta = blockIdx.x;
    int lane = tid & 31, wid = tid >> 5;
    int m = wid & 3, nh = wid >> 2;
    int q = lane & 3, g = lane >> 2;
    int b0 = cta * 64;

    const u32* Bsrc = (L == 0) ? g_Bf_hh0 : g_Bf_hh1;
    for (int i = tid; i < 41600; i += 256) sm[i] = Bsrc[i];
    for (int i = tid; i < 6656; i += 256) sm[A_OFF + i] = 0;
    __syncthreads();

    float cst[25];
    #pragma unroll
    for (int i = 0; i < 25; i++) cst[i] = 0.f;

    int rowA = m * 16 + g + ((q & 1) ? 8 : 0);  // the (row) this thread's cells live on
    int bglob = b0 + rowA;

    for (int t = 0; t < TT; t++) {
        if (L == 0 && tid < 64) tok[tid] = x[(b0 + tid) * TT + t];
        u32 ahi[26], alo[26];
        load_afrags(Ah, Al, m, lane, ahi, alo);
        __syncthreads();

        const float4* gxrow = (L == 1) ? (g_gx + ((size_t)t * BB + bglob) * HH) : (const float4*)0;
        int tk = (L == 0) ? tok[rowA] : 0;

        #pragma unroll
        for (int ntl = 0; ntl < 25; ntl++) {
            int nta = nh * 25 + ntl;
            float c[4];
            mma_tile(c, ahi, alo, Bh + nta * NTBLK, Bl + nta * NTBLK, lane);

            float s0 = (q & 1) ? c[0] : c[2];
            float s1 = (q & 1) ? c[1] : c[3];
            float x0 = __shfl_xor_sync(0xFFFFFFFFu, s0, 1);
            float x1 = __shfl_xor_sync(0xFFFFFFFFu, s1, 1);
            float gi = (q & 1) ? x0 : c[0];
            float gf = (q & 1) ? x1 : c[1];
            float gg = (q & 1) ? c[2] : x0;
            float go = (q & 1) ? c[3] : x1;

            int hg = nh * 50 + ntl * 2 + (q >> 1);
            float4 base = (L == 0) ? g_tab0[tk * HH + hg] : gxrow[hg];
            gi += base.x; gf += base.y; gg += base.z; go += base.w;

            float iv = sig_(gi), fv = sig_(gf), gv = tanh_(gg), ov = sig_(go);
            float cn = fv * cst[ntl] + iv * gv;
            cst[ntl] = cn;
            float hn = ov * tanh_(cn);

            u16 hb = bf16b(hn);
            u16 lb = bf16b(hn - bf16f(hb));
            ((u16*)Ah)[rowA * 104 + hg] = hb;
            ((u16*)Al)[rowA * 104 + hg] = lb;
            if (L == 1 && t == TT - 1) g_h2[hg * BB + bglob] = hn;
        }
        __syncthreads();

        if (L == 0) {
            uint4* d4 = (uint4*)g_h1f + (size_t)(t * 128 + cta) * 1664;
            const uint4* s4 = (const uint4*)(sm + A_OFF);
            for (int i = tid; i < 1664; i += 256) d4[i] = s4[i];
        }
    }
}

// ---------------- gx: W_ih1 * h1 + bias for all (t, b) on HMMA --------------
__global__ void __launch_bounds__(256, 1) gx_kernel() {
    extern __shared__ u32 sm[];
    u32* Bh = sm;
    u32* Bl = sm + IMG;
    float4* bias = (float4*)(sm + 41600);

    int tid = threadIdx.x;
    int lane = tid & 31, wid = tid >> 5;
    int m = wid & 3, nh = wid >> 2;
    int q = lane & 3, g = lane >> 2;

    for (int i = tid; i < 41600; i += 256) sm[i] = g_Bf_ih1[i];
    for (int i = tid; i < HH; i += 256) bias[i] = g_b1f4[i];
    __syncthreads();

    int rowA = m * 16 + g + ((q & 1) ? 8 : 0);

    for (int tile = blockIdx.x; tile < TT * 128; tile += 148) {
        int t = tile >> 7, bt = tile & 127;
        const u32* Ah = g_h1f + (size_t)tile * 6656;
        const u32* Al = Ah + 3328;
        u32 ahi[26], alo[26];
        load_afrags(Ah, Al, m, lane, ahi, alo);

        int bglob = bt * 64 + rowA;
        float4* dst = g_gx + ((size_t)t * BB + bglob) * HH;

        #pragma unroll
        for (int ntl = 0; ntl < 25; ntl++) {
            int nta = nh * 25 + ntl;
            float c[4];
            mma_tile(c, ahi, alo, Bh + nta * NTBLK, Bl + nta * NTBLK, lane);

            float s0 = (q & 1) ? c[0] : c[2];
            float s1 = (q & 1) ? c[1] : c[3];
            float x0 = __shfl_xor_sync(0xFFFFFFFFu, s0, 1);
            float x1 = __shfl_xor_sync(0xFFFFFFFFu, s1, 1);
            float gi = (q & 1) ? x0 : c[0];
            float gf = (q & 1) ? x1 : c[1];
            float gg = (q & 1) ? c[2] : x0;
            float go = (q & 1) ? c[3] : x1;

            int hg = nh * 50 + ntl * 2 + (q >> 1);
            float4 bv = bias[hg];
            dst[hg] = make_float4(gi + bv.x, gf + bv.y, gg + bv.z, go + bv.w);
        }
    }
}

// ---------------- final FC ----------------
__global__ void __launch_bounds__(256, 1)
fc_kernel(const float* __restrict__ fcW, const float* __restrict__ fcb,
          float* __restrict__ out) {
    __shared__ float Ws[VV * HH];
    __shared__ float bs[VV];
    int tid = threadIdx.x;
    for (int i = tid; i < VV * HH; i += 256) Ws[i] = fcW[i];
    if (tid < VV) bs[tid] = fcb[tid];
    __syncthreads();

    int b = blockIdx.x * 256 + tid;
    float hr[HH];
    #pragma unroll
    for (int k = 0; k < HH; k++) hr[k] = g_h2[k * BB + b];

    const float4* Ws4 = (const float4*)Ws;
    float4* out4 = (float4*)out;
    #pragma unroll 1
    for (int v4 = 0; v4 < 25; v4++) {
        float a[4];
        #pragma unroll
        for (int qq = 0; qq < 4; qq++) a[qq] = bs[v4 * 4 + qq];
        #pragma unroll
        for (int k4 = 0; k4 < 25; k4++) {
            #pragma unroll
            for (int qq = 0; qq < 4; qq++) {
                float4 w = Ws4[(v4 * 4 + qq) * 25 + k4];
                a[qq] += hr[k4 * 4 + 0] * w.x + hr[k4 * 4 + 1] * w.y +
                         hr[k4 * 4 + 2] * w.z + hr[k4 * 4 + 3] * w.w;
            }
        }
        out4[b * 25 + v4] = make_float4(a[0], a[1], a[2], a[3]);
    }
}

// ---------------- launch ----------------
extern "C" void kernel_launch(void* const* d_in, const int* in_sizes, int n_in,
                              void* d_out, int out_size) {
    const int*   x     = (const int*)  d_in[0];
    const float* embed = (const float*)d_in[1];
    const float* Wih0  = (const float*)d_in[2];
    const float* Whh0  = (const float*)d_in[3];
    const float* bih0  = (const float*)d_in[4];
    const float* bhh0  = (const float*)d_in[5];
    const float* Wih1  = (const float*)d_in[6];
    const float* Whh1  = (const float*)d_in[7];
    const float* bih1  = (const float*)d_in[8];
    const float* bhh1  = (const float*)d_in[9];
    const float* fcW   = (const float*)d_in[10];
    const float* fcb   = (const float*)d_in[11];
    float* out = (float*)d_out;

    cudaFuncSetAttribute(rec_kernel<0>, cudaFuncAttributeMaxDynamicSharedMemorySize, SMEM_REC);
    cudaFuncSetAttribute(rec_kernel<1>, cudaFuncAttributeMaxDynamicSharedMemorySize, SMEM_REC);
    cudaFuncSetAttribute(gx_kernel,     cudaFuncAttributeMaxDynamicSharedMemorySize, SMEM_GX);

    prep_kernel<<<160, 256>>>(embed, Wih0, Whh0, bih0, bhh0, Wih1, Whh1, bih1, bhh1);
    rec_kernel<0><<<128, 256, SMEM_REC>>>(x);
    gx_kernel<<<148, 256, SMEM_GX>>>();
    rec_kernel<1><<<128, 256, SMEM_REC>>>(x);
    fc_kernel<<<BB / 256, 256>>>(fcW, fcb, out);
}

// round 11
// speedup vs baseline: 2.0357x; 1.1547x over previous
#include <cuda_runtime.h>
#include <cuda_bf16.h>

typedef unsigned long long u64;
typedef unsigned int u32;
typedef unsigned short u16;

#define BB 8192
#define TT 80
#define HH 100
#define VV 100

#define IMG   20800           // u32 per B term-image (50 nt * 416)
#define NTBLK 416             // u32 per n-tile block
#define A_OFF   41600         // smem u32 offsets (rec)
#define AL_OFF  44928
#define TOK_OFF 48256
#define SMEM_REC (48320 * 4)
#define AGX_OFF 42000         // smem u32 offsets (gx): B | bias(400) | A-image
#define SMEM_GX ((AGX_OFF + 6656) * 4)

#define NTHR 512

// ---------------- device scratch ----------------
__device__ __align__(16) u32 g_Bf_hh0[41600];           // W_hh0 frag images (hi, lo)
__device__ __align__(16) u32 g_Bf_hh1[41600];           // W_hh1
__device__ __align__(16) u32 g_Bf_ih1[41600];           // W_ih1
__device__ __align__(16) float4 g_tab0[VV * HH];        // layer0 table, per (v,h): 4 gates
__device__ __align__(16) float4 g_b1f4[HH];             // layer1 bias per h
__device__ __align__(16) u32 g_h1f[(size_t)TT * 128 * 6656];  // h1 A-images [t*128+cta][hi|lo][64][52]
__device__ __align__(16) float4 g_gx[(size_t)TT * BB * HH];   // layer1 gate inputs per (t,b,h)
__device__ float g_h2[HH * BB];                         // final h [k][b]

// ---------------- helpers ----------------
__device__ __forceinline__ float sig_(float x) {
    return __fdividef(1.f, 1.f + __expf(-x));
}
__device__ __forceinline__ float tanh_(float x) {
    float e = __expf(2.f * x);
    return 1.f - __fdividef(2.f, e + 1.f);
}
static __device__ __forceinline__ u16 bf16b(float f) {
    return __bfloat16_as_ushort(__float2bfloat16_rn(f));
}
static __device__ __forceinline__ float bf16f(u16 b) {
    return __uint_as_float((u32)b << 16);
}

#define MMA16(c, a, b0_, b1_) \
    asm volatile("mma.sync.aligned.m16n8k16.row.col.f32.bf16.bf16.f32 " \
        "{%0,%1,%2,%3},{%4,%5,%6,%7},{%8,%9},{%0,%1,%2,%3};" \
        : "+f"((c)[0]), "+f"((c)[1]), "+f"((c)[2]), "+f"((c)[3]) \
        : "r"((a)[0]), "r"((a)[1]), "r"((a)[2]), "r"((a)[3]), "r"(b0_), "r"(b1_))

#define MMA8(c, a0_, a1_, b0_) \
    asm volatile("mma.sync.aligned.m16n8k8.row.col.f32.bf16.bf16.f32 " \
        "{%0,%1,%2,%3},{%4,%5},{%6},{%0,%1,%2,%3};" \
        : "+f"((c)[0]), "+f"((c)[1]), "+f"((c)[2]), "+f"((c)[3]) \
        : "r"(a0_), "r"(a1_), "r"(b0_))

// A fragments from a [64 rows][52 k-pairs] u32 pair-image
__device__ __forceinline__ void load_afrags(const u32* Ah, const u32* Al,
                                            int m, int lane, u32 ahi[26], u32 alo[26]) {
    int g = lane >> 2, q = lane & 3;
    int r0 = (m * 16 + g) * 52, r8 = r0 + 8 * 52;
    #pragma unroll
    for (int kt = 0; kt < 6; kt++) {
        int kp = kt * 8 + q;
        ahi[kt * 4 + 0] = Ah[r0 + kp];     ahi[kt * 4 + 1] = Ah[r8 + kp];
        ahi[kt * 4 + 2] = Ah[r0 + kp + 4]; ahi[kt * 4 + 3] = Ah[r8 + kp + 4];
        alo[kt * 4 + 0] = Al[r0 + kp];     alo[kt * 4 + 1] = Al[r8 + kp];
        alo[kt * 4 + 2] = Al[r0 + kp + 4]; alo[kt * 4 + 3] = Al[r8 + kp + 4];
    }
    ahi[24] = Ah[r0 + 48 + q]; ahi[25] = Ah[r8 + 48 + q];
    alo[24] = Al[r0 + 48 + q]; alo[25] = Al[r8 + 48 + q];
}

// One n8 tile x K=104, 3-term split on 3 independent accumulator chains
__device__ __forceinline__ void mma_tile(float c[4], const u32 ahi[26], const u32 alo[26],
                                         const u32* Bh, const u32* Bl, int lane) {
    float cA[4] = {0.f, 0.f, 0.f, 0.f};
    float cB[4] = {0.f, 0.f, 0.f, 0.f};
    float cC[4] = {0.f, 0.f, 0.f, 0.f};
    #pragma unroll
    for (int kt = 0; kt < 6; kt++) {
        u64 bh = *(const u64*)(Bh + kt * 64 + lane * 2);
        u64 bl = *(const u64*)(Bl + kt * 64 + lane * 2);
        u32 bh0 = (u32)bh, bh1 = (u32)(bh >> 32);
        u32 bl0 = (u32)bl, bl1 = (u32)(bl >> 32);
        MMA16(cA, ahi + kt * 4, bh0, bh1);
        MMA16(cB, ahi + kt * 4, bl0, bl1);
        MMA16(cC, alo + kt * 4, bh0, bh1);
    }
    u32 bh8 = Bh[384 + lane], bl8 = Bl[384 + lane];
    MMA8(cA, ahi[24], ahi[25], bh8);
    MMA8(cB, ahi[24], ahi[25], bl8);
    MMA8(cC, alo[24], alo[25], bh8);
    #pragma unroll
    for (int i = 0; i < 4; i++) c[i] = (cA[i] + cB[i]) + cC[i];
}

// ---------------- prep ----------------
__global__ void prep_kernel(const float* __restrict__ embed,
                            const float* __restrict__ Wih0,
                            const float* __restrict__ Whh0,
                            const float* __restrict__ bih0,
                            const float* __restrict__ bhh0,
                            const float* __restrict__ Wih1,
                            const float* __restrict__ Whh1,
                            const float* __restrict__ bih1,
                            const float* __restrict__ bhh1) {
    int stride = gridDim.x * blockDim.x;
    int gid = blockIdx.x * blockDim.x + threadIdx.x;

    // B fragment images, n' = 4h+gate ordering, j(n') = (n'&3)*100 + (n'>>2)
    for (int idx = gid; idx < 3 * 41600; idx += stride) {
        int sel = idx / 41600;
        int r = idx % 41600;
        const float* W = sel == 0 ? Whh0 : (sel == 1 ? Whh1 : Wih1);
        u32* dst = sel == 0 ? g_Bf_hh0 : (sel == 1 ? g_Bf_hh1 : g_Bf_ih1);
        int img = r / IMG;
        int r2 = r % IMG;
        int nt = r2 / NTBLK, o = r2 % NTBLK;
        int lane, kb;
        if (o < 384) {
            int kt = o >> 6; int w = o & 63;
            lane = w >> 1;
            kb = kt * 16 + 2 * (lane & 3) + (w & 1) * 8;
        } else {
            lane = o - 384;
            kb = 96 + 2 * (lane & 3);
        }
        int np = nt * 8 + (lane >> 2);
        int j = (np & 3) * 100 + (np >> 2);
        float w0 = (kb < HH) ? W[j * HH + kb] : 0.f;
        float w1 = (kb + 1 < HH) ? W[j * HH + kb + 1] : 0.f;
        u32 v;
        if (img == 0) {
            v = (u32)bf16b(w0) | ((u32)bf16b(w1) << 16);
        } else {
            float q0 = w0 - bf16f(bf16b(w0));
            float q1 = w1 - bf16f(bf16b(w1));
            v = (u32)bf16b(q0) | ((u32)bf16b(q1) << 16);
        }
        dst[r] = v;
    }
    // layer0 table: per (v,h) the 4 gate values of W_ih0*emb[v] + biases
    for (int idx = gid; idx < VV * HH; idx += stride) {
        int v = idx / HH, h = idx % HH;
        float tv[4];
        #pragma unroll
        for (int gt = 0; gt < 4; gt++) {
            int j = gt * HH + h;
            float s = bih0[j] + bhh0[j];
            #pragma unroll
            for (int e = 0; e < 8; e++) s += Wih0[j * 8 + e] * embed[v * 8 + e];
            tv[gt] = s;
        }
        g_tab0[idx] = make_float4(tv[0], tv[1], tv[2], tv[3]);
    }
    // layer1 bias per h
    for (int idx = gid; idx < HH; idx += stride) {
        g_b1f4[idx] = make_float4(bih1[idx] + bhh1[idx],
                                  bih1[HH + idx] + bhh1[HH + idx],
                                  bih1[2 * HH + idx] + bhh1[2 * HH + idx],
                                  bih1[3 * HH + idx] + bhh1[3 * HH + idx]);
    }
}

// ---------------- recurrent layer (L=0: layer0, L=1: layer1) ----------------
// 512 threads: warp -> (m = wid&3, nh = wid>>2); nh owns 13/13/12/12 n-tiles.
template <int L>
__global__ void __launch_bounds__(NTHR, 1) rec_kernel(const int* __restrict__ x) {
    extern __shared__ u32 sm[];
    u32* Bh = sm;
    u32* Bl = sm + IMG;
    u32* Ah = sm + A_OFF;
    u32* Al = sm + AL_OFF;
    int* tok = (int*)(sm + TOK_OFF);

    int tid = threadIdx.x, cta = blockIdx.x;
    int lane = tid & 31, wid = tid >> 5;
    int m = wid & 3, nh = wid >> 2;
    int q = lane & 3;
    int b0 = cta * 64;
    const int base_nt = nh * 13 - (nh == 3 ? 1 : 0);   // 0,13,26,38
    const int cnt = (nh < 2) ? 13 : 12;

    const u32* Bsrc = (L == 0) ? g_Bf_hh0 : g_Bf_hh1;
    for (int i = tid; i < 41600; i += NTHR) sm[i] = Bsrc[i];
    for (int i = tid; i < 6656; i += NTHR) sm[A_OFF + i] = 0;
    __syncthreads();

    float cst[13];
    #pragma unroll
    for (int i = 0; i < 13; i++) cst[i] = 0.f;

    int rowA = m * 16 + (lane >> 2) + ((q & 1) ? 8 : 0);
    int bglob = b0 + rowA;

    for (int t = 0; t < TT; t++) {
        if (L == 0 && tid < 64) tok[tid] = x[(b0 + tid) * TT + t];
        u32 ahi[26], alo[26];
        load_afrags(Ah, Al, m, lane, ahi, alo);
        __syncthreads();

        const float4* gxrow = (L == 1) ? (g_gx + ((size_t)t * BB + bglob) * HH) : (const float4*)0;
        int tk = (L == 0) ? tok[rowA] : 0;

        #pragma unroll
        for (int ntl = 0; ntl < 13; ntl++) {
            if (ntl >= cnt) break;
            int nta = base_nt + ntl;
            float c[4];
            mma_tile(c, ahi, alo, Bh + nta * NTBLK, Bl + nta * NTBLK, lane);

            float s0 = (q & 1) ? c[0] : c[2];
            float s1 = (q & 1) ? c[1] : c[3];
            float x0 = __shfl_xor_sync(0xFFFFFFFFu, s0, 1);
            float x1 = __shfl_xor_sync(0xFFFFFFFFu, s1, 1);
            float gi = (q & 1) ? x0 : c[0];
            float gf = (q & 1) ? x1 : c[1];
            float gg = (q & 1) ? c[2] : x0;
            float go = (q & 1) ? c[3] : x1;

            int hg = nta * 2 + (q >> 1);
            float4 base = (L == 0) ? g_tab0[tk * HH + hg] : gxrow[hg];
            gi += base.x; gf += base.y; gg += base.z; go += base.w;

            float iv = sig_(gi), fv = sig_(gf), gv = tanh_(gg), ov = sig_(go);
            float cn = fv * cst[ntl] + iv * gv;
            cst[ntl] = cn;
            float hn = ov * tanh_(cn);

            u16 hb = bf16b(hn);
            u16 lb = bf16b(hn - bf16f(hb));
            ((u16*)Ah)[rowA * 104 + hg] = hb;
            ((u16*)Al)[rowA * 104 + hg] = lb;
            if (L == 1 && t == TT - 1) g_h2[hg * BB + bglob] = hn;
        }
        __syncthreads();

        if (L == 0) {
            uint4* d4 = (uint4*)g_h1f + (size_t)(t * 128 + cta) * 1664;
            const uint4* s4 = (const uint4*)(sm + A_OFF);
            for (int i = tid; i < 1664; i += NTHR) d4[i] = s4[i];
        }
    }
}

// ---------------- gx: W_ih1 * h1 + bias for all (t, b) on HMMA --------------
__global__ void __launch_bounds__(NTHR, 1) gx_kernel() {
    extern __shared__ u32 sm[];
    u32* Bh = sm;
    u32* Bl = sm + IMG;
    float4* bias = (float4*)(sm + 41600);
    u32* Ahs = sm + AGX_OFF;
    u32* Als = sm + AGX_OFF + 3328;

    int tid = threadIdx.x;
    int lane = tid & 31, wid = tid >> 5;
    int m = wid & 3, nh = wid >> 2;
    int q = lane & 3;
    const int base_nt = nh * 13 - (nh == 3 ? 1 : 0);
    const int cnt = (nh < 2) ? 13 : 12;

    for (int i = tid; i < 41600; i += NTHR) sm[i] = g_Bf_ih1[i];
    for (int i = tid; i < HH; i += NTHR) bias[i] = g_b1f4[i];

    int rowA = m * 16 + (lane >> 2) + ((q & 1) ? 8 : 0);

    for (int tile = blockIdx.x; tile < TT * 128; tile += 148) {
        int t = tile >> 7, bt = tile & 127;
        __syncthreads();
        {
            uint4* d4 = (uint4*)Ahs;
            const uint4* s4 = (const uint4*)(g_h1f + (size_t)tile * 6656);
            for (int i = tid; i < 1664; i += NTHR) d4[i] = s4[i];
        }
        __syncthreads();

        u32 ahi[26], alo[26];
        load_afrags(Ahs, Als, m, lane, ahi, alo);

        int bglob = bt * 64 + rowA;
        float4* dst = g_gx + ((size_t)t * BB + bglob) * HH;

        #pragma unroll
        for (int ntl = 0; ntl < 13; ntl++) {
            if (ntl >= cnt) break;
            int nta = base_nt + ntl;
            float c[4];
            mma_tile(c, ahi, alo, Bh + nta * NTBLK, Bl + nta * NTBLK, lane);

            float s0 = (q & 1) ? c[0] : c[2];
            float s1 = (q & 1) ? c[1] : c[3];
            float x0 = __shfl_xor_sync(0xFFFFFFFFu, s0, 1);
            float x1 = __shfl_xor_sync(0xFFFFFFFFu, s1, 1);
            float gi = (q & 1) ? x0 : c[0];
            float gf = (q & 1) ? x1 : c[1];
            float gg = (q & 1) ? c[2] : x0;
            float go = (q & 1) ? c[3] : x1;

            int hg = nta * 2 + (q >> 1);
            float4 bv = bias[hg];
            dst[hg] = make_float4(gi + bv.x, gf + bv.y, gg + bv.z, go + bv.w);
        }
    }
}

// ---------------- final FC ----------------
__global__ void __launch_bounds__(256, 1)
fc_kernel(const float* __restrict__ fcW, const float* __restrict__ fcb,
          float* __restrict__ out) {
    __shared__ float Ws[VV * HH];
    __shared__ float bs[VV];
    int tid = threadIdx.x;
    for (int i = tid; i < VV * HH; i += 256) Ws[i] = fcW[i];
    if (tid < VV) bs[tid] = fcb[tid];
    __syncthreads();

    int b = blockIdx.x * 256 + tid;
    float hr[HH];
    #pragma unroll
    for (int k = 0; k < HH; k++) hr[k] = g_h2[k * BB + b];

    const float4* Ws4 = (const float4*)Ws;
    float4* out4 = (float4*)out;
    #pragma unroll 1
    for (int v4 = 0; v4 < 25; v4++) {
        float a[4];
        #pragma unroll
        for (int qq = 0; qq < 4; qq++) a[qq] = bs[v4 * 4 + qq];
        #pragma unroll
        for (int k4 = 0; k4 < 25; k4++) {
            #pragma unroll
            for (int qq = 0; qq < 4; qq++) {
                float4 w = Ws4[(v4 * 4 + qq) * 25 + k4];
                a[qq] += hr[k4 * 4 + 0] * w.x + hr[k4 * 4 + 1] * w.y +
                         hr[k4 * 4 + 2] * w.z + hr[k4 * 4 + 3] * w.w;
            }
        }
        out4[b * 25 + v4] = make_float4(a[0], a[1], a[2], a[3]);
    }
}

// ---------------- launch ----------------
extern "C" void kernel_launch(void* const* d_in, const int* in_sizes, int n_in,
                              void* d_out, int out_size) {
    const int*   x     = (const int*)  d_in[0];
    const float* embed = (const float*)d_in[1];
    const float* Wih0  = (const float*)d_in[2];
    const float* Whh0  = (const float*)d_in[3];
    const float* bih0  = (const float*)d_in[4];
    const float* bhh0  = (const float*)d_in[5];
    const float* Wih1  = (const float*)d_in[6];
    const float* Whh1  = (const float*)d_in[7];
    const float* bih1  = (const float*)d_in[8];
    const float* bhh1  = (const float*)d_in[9];
    const float* fcW   = (const float*)d_in[10];
    const float* fcb   = (const float*)d_in[11];
    float* out = (float*)d_out;

    cudaFuncSetAttribute(rec_kernel<0>, cudaFuncAttributeMaxDynamicSharedMemorySize, SMEM_REC);
    cudaFuncSetAttribute(rec_kernel<1>, cudaFuncAttributeMaxDynamicSharedMemorySize, SMEM_REC);
    cudaFuncSetAttribute(gx_kernel,     cudaFuncAttributeMaxDynamicSharedMemorySize, SMEM_GX);

    prep_kernel<<<160, 256>>>(embed, Wih0, Whh0, bih0, bhh0, Wih1, Whh1, bih1, bhh1);
    rec_kernel<0><<<128, NTHR, SMEM_REC>>>(x);
    gx_kernel<<<148, NTHR, SMEM_GX>>>();
    rec_kernel<1><<<128, NTHR, SMEM_REC>>>(x);
    fc_kernel<<<BB / 256, 256>>>(fcW, fcb, out);
}

// round 12
// speedup vs baseline: 2.5473x; 1.2513x over previous
#include <cuda_runtime.h>
#include <cuda_fp16.h>

typedef unsigned long long u64;
typedef unsigned int u32;
typedef unsigned short u16;

#define BB 8192
#define TT 80
#define HH 100
#define VV 100

#define BIMG  20800           // u32 per single-term B image (50 nt * 416)
#define NTBLK 416             // u32 per n-tile block
#define A_OFF   20800         // rec smem u32 offsets: B | Ah | Al | tok
#define AL_OFF  24128
#define TOK_OFF 27456
#define SMEM_REC (27520 * 4)
#define BIAS_OFF 20800        // gx smem: B | bias | Ah | Al
#define AGX_OFF  21200
#define SMEM_GX ((21200 + 6656) * 4)

#define NTHR 512

// ---------------- device scratch ----------------
__device__ __align__(16) u32 g_Bf_hh0[BIMG];            // W_hh0 fp16 frag image
__device__ __align__(16) u32 g_Bf_hh1[BIMG];            // W_hh1
__device__ __align__(16) u32 g_Bf_ih1[BIMG];            // W_ih1
__device__ __align__(16) float4 g_tab0[VV * HH];        // layer0 table, per (v,h): 4 gates
__device__ __align__(16) float4 g_b1f4[HH];             // layer1 bias per h
__device__ __align__(16) u32 g_h1f[(size_t)TT * 128 * 6656];  // h1 A-images [t*128+cta][hi|lo][64][52]
__device__ __align__(16) u64 g_gx[(size_t)TT * BB * HH];      // layer1 gate inputs, 4xfp16 per (t,b,h)
__device__ float g_h2[HH * BB];                         // final h [k][b]

// ---------------- helpers ----------------
__device__ __forceinline__ float sig_(float x) {
    return __fdividef(1.f, 1.f + __expf(-x));
}
__device__ __forceinline__ float tanh_(float x) {
    float e = __expf(2.f * x);
    return 1.f - __fdividef(2.f, e + 1.f);
}
static __device__ __forceinline__ u16 f16b(float f) {
    return __half_as_ushort(__float2half_rn(f));
}
static __device__ __forceinline__ float f16f(u16 b) {
    return __half2float(__ushort_as_half(b));
}

#define MMA16(c, a, b0_, b1_) \
    asm volatile("mma.sync.aligned.m16n8k16.row.col.f32.f16.f16.f32 " \
        "{%0,%1,%2,%3},{%4,%5,%6,%7},{%8,%9},{%0,%1,%2,%3};" \
        : "+f"((c)[0]), "+f"((c)[1]), "+f"((c)[2]), "+f"((c)[3]) \
        : "r"((a)[0]), "r"((a)[1]), "r"((a)[2]), "r"((a)[3]), "r"(b0_), "r"(b1_))

#define MMA8(c, a0_, a1_, b0_) \
    asm volatile("mma.sync.aligned.m16n8k8.row.col.f32.f16.f16.f32 " \
        "{%0,%1,%2,%3},{%4,%5},{%6},{%0,%1,%2,%3};" \
        : "+f"((c)[0]), "+f"((c)[1]), "+f"((c)[2]), "+f"((c)[3]) \
        : "r"(a0_), "r"(a1_), "r"(b0_))

// A fragments from a [64 rows][52 k-pairs] u32 pair-image
__device__ __forceinline__ void load_afrags(const u32* Ah, const u32* Al,
                                            int m, int lane, u32 ahi[26], u32 alo[26]) {
    int g = lane >> 2, q = lane & 3;
    int r0 = (m * 16 + g) * 52, r8 = r0 + 8 * 52;
    #pragma unroll
    for (int kt = 0; kt < 6; kt++) {
        int kp = kt * 8 + q;
        ahi[kt * 4 + 0] = Ah[r0 + kp];     ahi[kt * 4 + 1] = Ah[r8 + kp];
        ahi[kt * 4 + 2] = Ah[r0 + kp + 4]; ahi[kt * 4 + 3] = Ah[r8 + kp + 4];
        alo[kt * 4 + 0] = Al[r0 + kp];     alo[kt * 4 + 1] = Al[r8 + kp];
        alo[kt * 4 + 2] = Al[r0 + kp + 4]; alo[kt * 4 + 3] = Al[r8 + kp + 4];
    }
    ahi[24] = Ah[r0 + 48 + q]; ahi[25] = Ah[r8 + 48 + q];
    alo[24] = Al[r0 + 48 + q]; alo[25] = Al[r8 + 48 + q];
}

// One n8 tile x K=104: 2-term fp16 split (Ah*B + Al*B), 2 accumulator chains
__device__ __forceinline__ void mma_tile(float c[4], const u32 ahi[26], const u32 alo[26],
                                         const u32* B, int lane) {
    float cA[4] = {0.f, 0.f, 0.f, 0.f};
    float cB[4] = {0.f, 0.f, 0.f, 0.f};
    #pragma unroll
    for (int kt = 0; kt < 6; kt++) {
        u64 bh = *(const u64*)(B + kt * 64 + lane * 2);
        u32 b0 = (u32)bh, b1 = (u32)(bh >> 32);
        MMA16(cA, ahi + kt * 4, b0, b1);
        MMA16(cB, alo + kt * 4, b0, b1);
    }
    u32 b8 = B[384 + lane];
    MMA8(cA, ahi[24], ahi[25], b8);
    MMA8(cB, alo[24], alo[25], b8);
    #pragma unroll
    for (int i = 0; i < 4; i++) c[i] = cA[i] + cB[i];
}

// ---------------- prep ----------------
__global__ void prep_kernel(const float* __restrict__ embed,
                            const float* __restrict__ Wih0,
                            const float* __restrict__ Whh0,
                            const float* __restrict__ bih0,
                            const float* __restrict__ bhh0,
                            const float* __restrict__ Wih1,
                            const float* __restrict__ Whh1,
                            const float* __restrict__ bih1,
                            const float* __restrict__ bhh1) {
    int stride = gridDim.x * blockDim.x;
    int gid = blockIdx.x * blockDim.x + threadIdx.x;

    // B fragment images (single fp16 term), n' = 4h+gate; j(n') = (n'&3)*100 + (n'>>2)
    for (int idx = gid; idx < 3 * BIMG; idx += stride) {
        int sel = idx / BIMG;
        int r = idx % BIMG;
        const float* W = sel == 0 ? Whh0 : (sel == 1 ? Whh1 : Wih1);
        u32* dst = sel == 0 ? g_Bf_hh0 : (sel == 1 ? g_Bf_hh1 : g_Bf_ih1);
        int nt = r / NTBLK, o = r % NTBLK;
        int lane, kb;
        if (o < 384) {
            int kt = o >> 6; int w = o & 63;
            lane = w >> 1;
            kb = kt * 16 + 2 * (lane & 3) + (w & 1) * 8;
        } else {
            lane = o - 384;
            kb = 96 + 2 * (lane & 3);
        }
        int np = nt * 8 + (lane >> 2);
        int j = (np & 3) * 100 + (np >> 2);
        float w0 = (kb < HH) ? W[j * HH + kb] : 0.f;
        float w1 = (kb + 1 < HH) ? W[j * HH + kb + 1] : 0.f;
        dst[r] = (u32)f16b(w0) | ((u32)f16b(w1) << 16);
    }
    // layer0 table: per (v,h) the 4 gate values of W_ih0*emb[v] + biases
    for (int idx = gid; idx < VV * HH; idx += stride) {
        int v = idx / HH, h = idx % HH;
        float tv[4];
        #pragma unroll
        for (int gt = 0; gt < 4; gt++) {
            int j = gt * HH + h;
            float s = bih0[j] + bhh0[j];
            #pragma unroll
            for (int e = 0; e < 8; e++) s += Wih0[j * 8 + e] * embed[v * 8 + e];
            tv[gt] = s;
        }
        g_tab0[idx] = make_float4(tv[0], tv[1], tv[2], tv[3]);
    }
    // layer1 bias per h
    for (int idx = gid; idx < HH; idx += stride) {
        g_b1f4[idx] = make_float4(bih1[idx] + bhh1[idx],
                                  bih1[HH + idx] + bhh1[HH + idx],
                                  bih1[2 * HH + idx] + bhh1[2 * HH + idx],
                                  bih1[3 * HH + idx] + bhh1[3 * HH + idx]);
    }
}

// ---------------- recurrent layer (L=0: layer0, L=1: layer1) ----------------
// 512 threads: warp -> (m = wid&3, nh = wid>>2); nh owns 13/13/12/12 n-tiles.
template <int L>
__global__ void __launch_bounds__(NTHR, 1) rec_kernel(const int* __restrict__ x) {
    extern __shared__ u32 sm[];
    u32* Bf = sm;
    u32* Ah = sm + A_OFF;
    u32* Al = sm + AL_OFF;
    int* tok = (int*)(sm + TOK_OFF);

    int tid = threadIdx.x, cta = blockIdx.x;
    int lane = tid & 31, wid = tid >> 5;
    int m = wid & 3, nh = wid >> 2;
    int q = lane & 3;
    int b0 = cta * 64;
    const int base_nt = nh * 13 - (nh == 3 ? 1 : 0);   // 0,13,26,38
    const int cnt = (nh < 2) ? 13 : 12;

    const u32* Bsrc = (L == 0) ? g_Bf_hh0 : g_Bf_hh1;
    for (int i = tid; i < BIMG; i += NTHR) sm[i] = Bsrc[i];
    for (int i = tid; i < 6656; i += NTHR) sm[A_OFF + i] = 0;
    __syncthreads();

    float cst[13];
    #pragma unroll
    for (int i = 0; i < 13; i++) cst[i] = 0.f;

    int rowA = m * 16 + (lane >> 2) + ((q & 1) ? 8 : 0);
    int bglob = b0 + rowA;

    for (int t = 0; t < TT; t++) {
        if (L == 0 && tid < 64) tok[tid] = x[(b0 + tid) * TT + t];
        u32 ahi[26], alo[26];
        load_afrags(Ah, Al, m, lane, ahi, alo);
        __syncthreads();

        const u64* gxrow = (L == 1) ? (g_gx + ((size_t)t * BB + bglob) * HH) : (const u64*)0;
        int tk = (L == 0) ? tok[rowA] : 0;

        #pragma unroll
        for (int ntl = 0; ntl < 13; ntl++) {
            if (ntl >= cnt) break;
            int nta = base_nt + ntl;
            float c[4];
            mma_tile(c, ahi, alo, Bf + nta * NTBLK, lane);

            float s0 = (q & 1) ? c[0] : c[2];
            float s1 = (q & 1) ? c[1] : c[3];
            float x0 = __shfl_xor_sync(0xFFFFFFFFu, s0, 1);
            float x1 = __shfl_xor_sync(0xFFFFFFFFu, s1, 1);
            float gi = (q & 1) ? x0 : c[0];
            float gf = (q & 1) ? x1 : c[1];
            float gg = (q & 1) ? c[2] : x0;
            float go = (q & 1) ? c[3] : x1;

            int hg = nta * 2 + (q >> 1);
            if (L == 0) {
                float4 base = g_tab0[tk * HH + hg];
                gi += base.x; gf += base.y; gg += base.z; go += base.w;
            } else {
                u64 v = gxrow[hg];
                gi += f16f((u16)v);
                gf += f16f((u16)(v >> 16));
                gg += f16f((u16)(v >> 32));
                go += f16f((u16)(v >> 48));
            }

            float iv = sig_(gi), fv = sig_(gf), gv = tanh_(gg), ov = sig_(go);
            float cn = fv * cst[ntl] + iv * gv;
            cst[ntl] = cn;
            float hn = ov * tanh_(cn);

            u16 hb = f16b(hn);
            u16 lb = f16b(hn - f16f(hb));
            ((u16*)Ah)[rowA * 104 + hg] = hb;
            ((u16*)Al)[rowA * 104 + hg] = lb;
            if (L == 1 && t == TT - 1) g_h2[hg * BB + bglob] = hn;
        }
        __syncthreads();

        if (L == 0) {
            uint4* d4 = (uint4*)g_h1f + (size_t)(t * 128 + cta) * 1664;
            const uint4* s4 = (const uint4*)(sm + A_OFF);
            for (int i = tid; i < 1664; i += NTHR) d4[i] = s4[i];
        }
    }
}

// ---------------- gx: W_ih1 * h1 + bias for all (t, b) on HMMA --------------
__global__ void __launch_bounds__(NTHR, 1) gx_kernel() {
    extern __shared__ u32 sm[];
    u32* Bf = sm;
    float4* bias = (float4*)(sm + BIAS_OFF);
    u32* Ahs = sm + AGX_OFF;
    u32* Als = sm + AGX_OFF + 3328;

    int tid = threadIdx.x;
    int lane = tid & 31, wid = tid >> 5;
    int m = wid & 3, nh = wid >> 2;
    int q = lane & 3;
    const int base_nt = nh * 13 - (nh == 3 ? 1 : 0);
    const int cnt = (nh < 2) ? 13 : 12;

    for (int i = tid; i < BIMG; i += NTHR) sm[i] = g_Bf_ih1[i];
    for (int i = tid; i < HH; i += NTHR) bias[i] = g_b1f4[i];

    int rowA = m * 16 + (lane >> 2) + ((q & 1) ? 8 : 0);

    for (int tile = blockIdx.x; tile < TT * 128; tile += 148) {
        int t = tile >> 7, bt = tile & 127;
        __syncthreads();
        {
            uint4* d4 = (uint4*)Ahs;
            const uint4* s4 = (const uint4*)(g_h1f + (size_t)tile * 6656);
            for (int i = tid; i < 1664; i += NTHR) d4[i] = s4[i];
        }
        __syncthreads();

        u32 ahi[26], alo[26];
        load_afrags(Ahs, Als, m, lane, ahi, alo);

        int bglob = bt * 64 + rowA;
        u64* dst = g_gx + ((size_t)t * BB + bglob) * HH;

        #pragma unroll
        for (int ntl = 0; ntl < 13; ntl++) {
            if (ntl >= cnt) break;
            int nta = base_nt + ntl;
            float c[4];
            mma_tile(c, ahi, alo, Bf + nta * NTBLK, lane);

            float s0 = (q & 1) ? c[0] : c[2];
            float s1 = (q & 1) ? c[1] : c[3];
            float x0 = __shfl_xor_sync(0xFFFFFFFFu, s0, 1);
            float x1 = __shfl_xor_sync(0xFFFFFFFFu, s1, 1);
            float gi = (q & 1) ? x0 : c[0];
            float gf = (q & 1) ? x1 : c[1];
            float gg = (q & 1) ? c[2] : x0;
            float go = (q & 1) ? c[3] : x1;

            int hg = nta * 2 + (q >> 1);
            float4 bv = bias[hg];
            u64 v = (u64)f16b(gi + bv.x)
                  | ((u64)f16b(gf + bv.y) << 16)
                  | ((u64)f16b(gg + bv.z) << 32)
                  | ((u64)f16b(go + bv.w) << 48);
            dst[hg] = v;
        }
    }
}

// ---------------- final FC ----------------
__global__ void __launch_bounds__(256, 1)
fc_kernel(const float* __restrict__ fcW, const float* __restrict__ fcb,
          float* __restrict__ out) {
    __shared__ float Ws[VV * HH];
    __shared__ float bs[VV];
    int tid = threadIdx.x;
    for (int i = tid; i < VV * HH; i += 256) Ws[i] = fcW[i];
    if (tid < VV) bs[tid] = fcb[tid];
    __syncthreads();

    int b = blockIdx.x * 256 + tid;
    float hr[HH];
    #pragma unroll
    for (int k = 0; k < HH; k++) hr[k] = g_h2[k * BB + b];

    const float4* Ws4 = (const float4*)Ws;
    float4* out4 = (float4*)out;
    #pragma unroll 1
    for (int v4 = 0; v4 < 25; v4++) {
        float a[4];
        #pragma unroll
        for (int qq = 0; qq < 4; qq++) a[qq] = bs[v4 * 4 + qq];
        #pragma unroll
        for (int k4 = 0; k4 < 25; k4++) {
            #pragma unroll
            for (int qq = 0; qq < 4; qq++) {
                float4 w = Ws4[(v4 * 4 + qq) * 25 + k4];
                a[qq] += hr[k4 * 4 + 0] * w.x + hr[k4 * 4 + 1] * w.y +
                         hr[k4 * 4 + 2] * w.z + hr[k4 * 4 + 3] * w.w;
            }
        }
        out4[b * 25 + v4] = make_float4(a[0], a[1], a[2], a[3]);
    }
}

// ---------------- launch ----------------
extern "C" void kernel_launch(void* const* d_in, const int* in_sizes, int n_in,
                              void* d_out, int out_size) {
    const int*   x     = (const int*)  d_in[0];
    const float* embed = (const float*)d_in[1];
    const float* Wih0  = (const float*)d_in[2];
    const float* Whh0  = (const float*)d_in[3];
    const float* bih0  = (const float*)d_in[4];
    const float* bhh0  = (const float*)d_in[5];
    const float* Wih1  = (const float*)d_in[6];
    const float* Whh1  = (const float*)d_in[7];
    const float* bih1  = (const float*)d_in[8];
    const float* bhh1  = (const float*)d_in[9];
    const float* fcW   = (const float*)d_in[10];
    const float* fcb   = (const float*)d_in[11];
    float* out = (float*)d_out;

    cudaFuncSetAttribute(rec_kernel<0>, cudaFuncAttributeMaxDynamicSharedMemorySize, SMEM_REC);
    cudaFuncSetAttribute(rec_kernel<1>, cudaFuncAttributeMaxDynamicSharedMemorySize, SMEM_REC);
    cudaFuncSetAttribute(gx_kernel,     cudaFuncAttributeMaxDynamicSharedMemorySize, SMEM_GX);

    prep_kernel<<<160, 256>>>(embed, Wih0, Whh0, bih0, bhh0, Wih1, Whh1, bih1, bhh1);
    rec_kernel<0><<<128, NTHR, SMEM_REC>>>(x);
    gx_kernel<<<148, NTHR, SMEM_GX>>>();
    rec_kernel<1><<<128, NTHR, SMEM_REC>>>(x);
    fc_kernel<<<BB / 256, 256>>>(fcW, fcb, out);
}

// round 14
// speedup vs baseline: 2.6529x; 1.0415x over previous
#include <cuda_runtime.h>
#include <cuda_fp16.h>

typedef unsigned long long u64;
typedef unsigned int u32;
typedef unsigned short u16;

#define BB 8192
#define TT 80
#define HH 100
#define VV 100

#define BIMG  20800           // u32 per single-term B image (50 nt * 416)
#define NTBLK 416             // u32 per n-tile block
#define A_OFF 20800           // rec smem: B | A ping-pong (2 x 3328: Ah 1664 | Al 1664)
#define SMEM_REC ((20800 + 6656) * 4)
#define BIAS_OFF 20800        // gx smem: B | bias(400) | A(3328)
#define AGX_OFF  21200
#define SMEM_GX ((21200 + 3328) * 4)

#define NTHR 256

// ---------------- device scratch ----------------
__device__ __align__(16) u32 g_Bf_hh0[BIMG];            // W_hh0 fp16 frag image
__device__ __align__(16) u32 g_Bf_hh1[BIMG];            // W_hh1
__device__ __align__(16) u32 g_Bf_ih1[BIMG];            // W_ih1
__device__ __align__(16) float4 g_tab0[VV * HH];        // layer0 table, per (v,h): 4 gates
__device__ __align__(16) float4 g_b1f4[HH];             // layer1 bias per h
__device__ __align__(16) u32 g_h1f[(size_t)TT * 256 * 3328];  // h1 A-images [t*256+cta][Ah|Al][32][52]
__device__ __align__(16) u64 g_gx[(size_t)TT * BB * HH];      // layer1 gate inputs, 4xfp16 per (t,b,h)
__device__ float g_h2[HH * BB];                         // final h [k][b]

// ---------------- helpers ----------------
__device__ __forceinline__ float sig_(float x) {
    return __fdividef(1.f, 1.f + __expf(-x));
}
__device__ __forceinline__ float tanh_(float x) {
    float e = __expf(2.f * x);
    return 1.f - __fdividef(2.f, e + 1.f);
}
static __device__ __forceinline__ u16 f16b(float f) {
    return __half_as_ushort(__float2half_rn(f));
}
static __device__ __forceinline__ float f16f(u16 b) {
    return __half2float(__ushort_as_half(b));
}

#define MMA16(c, a, b0_, b1_) \
    asm volatile("mma.sync.aligned.m16n8k16.row.col.f32.f16.f16.f32 " \
        "{%0,%1,%2,%3},{%4,%5,%6,%7},{%8,%9},{%0,%1,%2,%3};" \
        : "+f"((c)[0]), "+f"((c)[1]), "+f"((c)[2]), "+f"((c)[3]) \
        : "r"((a)[0]), "r"((a)[1]), "r"((a)[2]), "r"((a)[3]), "r"(b0_), "r"(b1_))

#define MMA8(c, a0_, a1_, b0_) \
    asm volatile("mma.sync.aligned.m16n8k8.row.col.f32.f16.f16.f32 " \
        "{%0,%1,%2,%3},{%4,%5},{%6},{%0,%1,%2,%3};" \
        : "+f"((c)[0]), "+f"((c)[1]), "+f"((c)[2]), "+f"((c)[3]) \
        : "r"(a0_), "r"(a1_), "r"(b0_))

// A fragments from a [32 rows][52 k-pairs] u32 pair-image (Ah at 0, Al at +1664)
__device__ __forceinline__ void load_afrags(const u32* Ah, const u32* Al,
                                            int m, int lane, u32 ahi[26], u32 alo[26]) {
    int g = lane >> 2, q = lane & 3;
    int r0 = (m * 16 + g) * 52, r8 = r0 + 8 * 52;
    #pragma unroll
    for (int kt = 0; kt < 6; kt++) {
        int kp = kt * 8 + q;
        ahi[kt * 4 + 0] = Ah[r0 + kp];     ahi[kt * 4 + 1] = Ah[r8 + kp];
        ahi[kt * 4 + 2] = Ah[r0 + kp + 4]; ahi[kt * 4 + 3] = Ah[r8 + kp + 4];
        alo[kt * 4 + 0] = Al[r0 + kp];     alo[kt * 4 + 1] = Al[r8 + kp];
        alo[kt * 4 + 2] = Al[r0 + kp + 4]; alo[kt * 4 + 3] = Al[r8 + kp + 4];
    }
    ahi[24] = Ah[r0 + 48 + q]; ahi[25] = Ah[r8 + 48 + q];
    alo[24] = Al[r0 + 48 + q]; alo[25] = Al[r8 + 48 + q];
}

// One n8 tile x K=104: 2-term fp16 split (Ah*B + Al*B), 2 accumulator chains
__device__ __forceinline__ void mma_tile(float c[4], const u32 ahi[26], const u32 alo[26],
                                         const u32* B, int lane) {
    float cA[4] = {0.f, 0.f, 0.f, 0.f};
    float cB[4] = {0.f, 0.f, 0.f, 0.f};
    #pragma unroll
    for (int kt = 0; kt < 6; kt++) {
        u64 bh = *(const u64*)(B + kt * 64 + lane * 2);
        u32 b0 = (u32)bh, b1 = (u32)(bh >> 32);
        MMA16(cA, ahi + kt * 4, b0, b1);
        MMA16(cB, alo + kt * 4, b0, b1);
    }
    u32 b8 = B[384 + lane];
    MMA8(cA, ahi[24], ahi[25], b8);
    MMA8(cB, alo[24], alo[25], b8);
    #pragma unroll
    for (int i = 0; i < 4; i++) c[i] = cA[i] + cB[i];
}

// ---------------- prep ----------------
__global__ void prep_kernel(const float* __restrict__ embed,
                            const float* __restrict__ Wih0,
                            const float* __restrict__ Whh0,
                            const float* __restrict__ bih0,
                            const float* __restrict__ bhh0,
                            const float* __restrict__ Wih1,
                            const float* __restrict__ Whh1,
                            const float* __restrict__ bih1,
                            const float* __restrict__ bhh1) {
    int stride = gridDim.x * blockDim.x;
    int gid = blockIdx.x * blockDim.x + threadIdx.x;

    // B fragment images (single fp16 term), n' = 4h+gate; j(n') = (n'&3)*100 + (n'>>2)
    for (int idx = gid; idx < 3 * BIMG; idx += stride) {
        int sel = idx / BIMG;
        int r = idx % BIMG;
        const float* W = sel == 0 ? Whh0 : (sel == 1 ? Whh1 : Wih1);
        u32* dst = sel == 0 ? g_Bf_hh0 : (sel == 1 ? g_Bf_hh1 : g_Bf_ih1);
        int nt = r / NTBLK, o = r % NTBLK;
        int lane, kb;
        if (o < 384) {
            int kt = o >> 6; int w = o & 63;
            lane = w >> 1;
            kb = kt * 16 + 2 * (lane & 3) + (w & 1) * 8;
        } else {
            lane = o - 384;
            kb = 96 + 2 * (lane & 3);
        }
        int np = nt * 8 + (lane >> 2);
        int j = (np & 3) * 100 + (np >> 2);
        float w0 = (kb < HH) ? W[j * HH + kb] : 0.f;
        float w1 = (kb + 1 < HH) ? W[j * HH + kb + 1] : 0.f;
        dst[r] = (u32)f16b(w0) | ((u32)f16b(w1) << 16);
    }
    // layer0 table: per (v,h) the 4 gate values of W_ih0*emb[v] + biases
    for (int idx = gid; idx < VV * HH; idx += stride) {
        int v = idx / HH, h = idx % HH;
        float tv[4];
        #pragma unroll
        for (int gt = 0; gt < 4; gt++) {
            int j = gt * HH + h;
            float s = bih0[j] + bhh0[j];
            #pragma unroll
            for (int e = 0; e < 8; e++) s += Wih0[j * 8 + e] * embed[v * 8 + e];
            tv[gt] = s;
        }
        g_tab0[idx] = make_float4(tv[0], tv[1], tv[2], tv[3]);
    }
    // layer1 bias per h
    for (int idx = gid; idx < HH; idx += stride) {
        g_b1f4[idx] = make_float4(bih1[idx] + bhh1[idx],
                                  bih1[HH + idx] + bhh1[HH + idx],
                                  bih1[2 * HH + idx] + bhh1[2 * HH + idx],
                                  bih1[3 * HH + idx] + bhh1[3 * HH + idx]);
    }
}

// ---------------- recurrent layer (L=0: layer0, L=1: layer1) ----------------
// 256 threads, 2 CTAs/SM: warp -> (m = wid&1, nh = wid>>1). 32 batch rows/CTA.
// Ping-pong A buffers -> ONE __syncthreads per step.
template <int L>
__global__ void __launch_bounds__(NTHR, 2) rec_kernel(const int* __restrict__ x) {
    extern __shared__ u32 sm[];
    u32* Bf = sm;

    int tid = threadIdx.x, cta = blockIdx.x;
    int lane = tid & 31, wid = tid >> 5;
    int m = wid & 1, nh = wid >> 1;
    int q = lane & 3;
    int b0 = cta * 32;
    const int base_nt = nh * 13 - (nh == 3 ? 1 : 0);   // 0,13,26,38
    const int cnt = (nh < 2) ? 13 : 12;

    const u32* Bsrc = (L == 0) ? g_Bf_hh0 : g_Bf_hh1;
    for (int i = tid; i < BIMG; i += NTHR) sm[i] = Bsrc[i];
    // Zero BOTH ping-pong buffers: pad columns (hg 100..103) are never written
    // during steps; they must be zero in BOTH buffers or fp16 NaN garbage
    // enters the MMA (NaN * 0 = NaN) — this was the R12 replay-divergence bug.
    for (int i = tid; i < 6656; i += NTHR) sm[A_OFF + i] = 0;
    __syncthreads();

    float cst[13];
    #pragma unroll
    for (int i = 0; i < 13; i++) cst[i] = 0.f;

    int rowA = m * 16 + (lane >> 2) + ((q & 1) ? 8 : 0);
    int bglob = b0 + rowA;
    const int* xrow = x + bglob * TT;

    for (int t = 0; t < TT; t++) {
        int rb = t & 1, wb = rb ^ 1;
        const u32* Ahr = sm + A_OFF + rb * 3328;
        const u32* Alr = Ahr + 1664;
        u16* Ahw = (u16*)(sm + A_OFF + wb * 3328);
        u16* Alw = Ahw + 3328;

        u32 ahi[26], alo[26];
        load_afrags(Ahr, Alr, m, lane, ahi, alo);

        const u64* gxrow = (L == 1) ? (g_gx + ((size_t)t * BB + bglob) * HH) : (const u64*)0;
        int tk = (L == 0) ? xrow[t] : 0;

        #pragma unroll
        for (int ntl = 0; ntl < 13; ntl++) {
            if (ntl >= cnt) break;
            int nta = base_nt + ntl;
            float c[4];
            mma_tile(c, ahi, alo, Bf + nta * NTBLK, lane);

            float s0 = (q & 1) ? c[0] : c[2];
            float s1 = (q & 1) ? c[1] : c[3];
            float x0 = __shfl_xor_sync(0xFFFFFFFFu, s0, 1);
            float x1 = __shfl_xor_sync(0xFFFFFFFFu, s1, 1);
            float gi = (q & 1) ? x0 : c[0];
            float gf = (q & 1) ? x1 : c[1];
            float gg = (q & 1) ? c[2] : x0;
            float go = (q & 1) ? c[3] : x1;

            int hg = nta * 2 + (q >> 1);
            if (L == 0) {
                float4 base = g_tab0[tk * HH + hg];
                gi += base.x; gf += base.y; gg += base.z; go += base.w;
            } else {
                u64 v = gxrow[hg];
                gi += f16f((u16)v);
                gf += f16f((u16)(v >> 16));
                gg += f16f((u16)(v >> 32));
                go += f16f((u16)(v >> 48));
            }

            float iv = sig_(gi), fv = sig_(gf), gv = tanh_(gg), ov = sig_(go);
            float cn = fv * cst[ntl] + iv * gv;
            cst[ntl] = cn;
            float hn = ov * tanh_(cn);

            u16 hb = f16b(hn);
            u16 lb = f16b(hn - f16f(hb));
            Ahw[rowA * 104 + hg] = hb;
            Alw[rowA * 104 + hg] = lb;
            if (L == 1 && t == TT - 1) g_h2[hg * BB + bglob] = hn;
        }
        __syncthreads();   // single per-step sync: orders wb writes before next step's reads

        if (L == 0) {
            uint4* d4 = (uint4*)g_h1f + (size_t)(t * 256 + cta) * 832;
            const uint4* s4 = (const uint4*)(sm + A_OFF + wb * 3328);
            for (int i = tid; i < 832; i += NTHR) d4[i] = s4[i];
        }
    }
}

// ---------------- gx: W_ih1 * h1 + bias for all (t, b) on HMMA --------------
// 256 threads, 2 CTAs/SM, 32-row tiles.
__global__ void __launch_bounds__(NTHR, 2) gx_kernel() {
    extern __shared__ u32 sm[];
    u32* Bf = sm;
    float4* bias = (float4*)(sm + BIAS_OFF);
    u32* Ahs = sm + AGX_OFF;
    u32* Als = Ahs + 1664;

    int tid = threadIdx.x;
    int lane = tid & 31, wid = tid >> 5;
    int m = wid & 1, nh = wid >> 1;
    int q = lane & 3;
    const int base_nt = nh * 13 - (nh == 3 ? 1 : 0);
    const int cnt = (nh < 2) ? 13 : 12;

    for (int i = tid; i < BIMG; i += NTHR) sm[i] = g_Bf_ih1[i];
    for (int i = tid; i < HH; i += NTHR) bias[i] = g_b1f4[i];

    int rowA = m * 16 + (lane >> 2) + ((q & 1) ? 8 : 0);

    for (int tile = blockIdx.x; tile < TT * 256; tile += 296) {
        int t = tile >> 8, bt = tile & 255;
        __syncthreads();
        {
            uint4* d4 = (uint4*)Ahs;
            const uint4* s4 = (const uint4*)(g_h1f + (size_t)tile * 3328);
            for (int i = tid; i < 832; i += NTHR) d4[i] = s4[i];
        }
        __syncthreads();

        u32 ahi[26], alo[26];
        load_afrags(Ahs, Als, m, lane, ahi, alo);

        int bglob = bt * 32 + rowA;
        u64* dst = g_gx + ((size_t)t * BB + bglob) * HH;

        #pragma unroll
        for (int ntl = 0; ntl < 13; ntl++) {
            if (ntl >= cnt) break;
            int nta = base_nt + ntl;
            float c[4];
            mma_tile(c, ahi, alo, Bf + nta * NTBLK, lane);

            float s0 = (q & 1) ? c[0] : c[2];
            float s1 = (q & 1) ? c[1] : c[3];
            float x0 = __shfl_xor_sync(0xFFFFFFFFu, s0, 1);
            float x1 = __shfl_xor_sync(0xFFFFFFFFu, s1, 1);
            float gi = (q & 1) ? x0 : c[0];
            float gf = (q & 1) ? x1 : c[1];
            float gg = (q & 1) ? c[2] : x0;
            float go = (q & 1) ? c[3] : x1;

            int hg = nta * 2 + (q >> 1);
            float4 bv = bias[hg];
            u64 v = (u64)f16b(gi + bv.x)
                  | ((u64)f16b(gf + bv.y) << 16)
                  | ((u64)f16b(gg + bv.z) << 32)
                  | ((u64)f16b(go + bv.w) << 48);
            dst[hg] = v;
        }
    }
}

// ---------------- final FC ----------------
__global__ void __launch_bounds__(256, 1)
fc_kernel(const float* __restrict__ fcW, const float* __restrict__ fcb,
          float* __restrict__ out) {
    __shared__ float Ws[VV * HH];
    __shared__ float bs[VV];
    int tid = threadIdx.x;
    for (int i = tid; i < VV * HH; i += 256) Ws[i] = fcW[i];
    if (tid < VV) bs[tid] = fcb[tid];
    __syncthreads();

    int b = blockIdx.x * 256 + tid;
    float hr[HH];
    #pragma unroll
    for (int k = 0; k < HH; k++) hr[k] = g_h2[k * BB + b];

    const float4* Ws4 = (const float4*)Ws;
    float4* out4 = (float4*)out;
    #pragma unroll 1
    for (int v4 = 0; v4 < 25; v4++) {
        float a[4];
        #pragma unroll
        for (int qq = 0; qq < 4; qq++) a[qq] = bs[v4 * 4 + qq];
        #pragma unroll
        for (int k4 = 0; k4 < 25; k4++) {
            #pragma unroll
            for (int qq = 0; qq < 4; qq++) {
                float4 w = Ws4[(v4 * 4 + qq) * 25 + k4];
                a[qq] += hr[k4 * 4 + 0] * w.x + hr[k4 * 4 + 1] * w.y +
                         hr[k4 * 4 + 2] * w.z + hr[k4 * 4 + 3] * w.w;
            }
        }
        out4[b * 25 + v4] = make_float4(a[0], a[1], a[2], a[3]);
    }
}

// ---------------- launch ----------------
extern "C" void kernel_launch(void* const* d_in, const int* in_sizes, int n_in,
                              void* d_out, int out_size) {
    const int*   x     = (const int*)  d_in[0];
    const float* embed = (const float*)d_in[1];
    const float* Wih0  = (const float*)d_in[2];
    const float* Whh0  = (const float*)d_in[3];
    const float* bih0  = (const float*)d_in[4];
    const float* bhh0  = (const float*)d_in[5];
    const float* Wih1  = (const float*)d_in[6];
    const float* Whh1  = (const float*)d_in[7];
    const float* bih1  = (const float*)d_in[8];
    const float* bhh1  = (const float*)d_in[9];
    const float* fcW   = (const float*)d_in[10];
    const float* fcb   = (const float*)d_in[11];
    float* out = (float*)d_out;

    cudaFuncSetAttribute(rec_kernel<0>, cudaFuncAttributeMaxDynamicSharedMemorySize, SMEM_REC);
    cudaFuncSetAttribute(rec_kernel<1>, cudaFuncAttributeMaxDynamicSharedMemorySize, SMEM_REC);
    cudaFuncSetAttribute(gx_kernel,     cudaFuncAttributeMaxDynamicSharedMemorySize, SMEM_GX);

    prep_kernel<<<160, 256>>>(embed, Wih0, Whh0, bih0, bhh0, Wih1, Whh1, bih1, bhh1);
    rec_kernel<0><<<256, NTHR, SMEM_REC>>>(x);
    gx_kernel<<<296, NTHR, SMEM_GX>>>();
    rec_kernel<1><<<256, NTHR, SMEM_REC>>>(x);
    fc_kernel<<<BB / 256, 256>>>(fcW, fcb, out);
}

// round 15
// speedup vs baseline: 2.8512x; 1.0747x over previous
#include <cuda_runtime.h>
#include <cuda_fp16.h>

typedef unsigned long long u64;
typedef unsigned int u32;
typedef unsigned short u16;

#define BB 8192
#define TT 80
#define HH 100
#define VV 100

#define BIMG  20800           // u32 per single-term B image (50 nt * 416)
#define NTBLK 416             // u32 per n-tile block
#define A_OFF 20800           // rec smem: B | A ping-pong (2 x 3328: Ah 1664 | Al 1664)
#define SMEM_REC ((20800 + 6656) * 4)
#define BIAS_OFF 20800        // gx smem: B | bias(400) | A(3328)
#define AGX_OFF  21200
#define SMEM_GX ((21200 + 3328) * 4)

#define NTHR 256

// ---------------- device scratch ----------------
__device__ __align__(16) u32 g_Bf_hh0[BIMG];            // W_hh0 fp16 frag image
__device__ __align__(16) u32 g_Bf_hh1[BIMG];            // W_hh1
__device__ __align__(16) u32 g_Bf_ih1[BIMG];            // W_ih1
__device__ __align__(16) float4 g_tab0[VV * HH];        // layer0 table, per (v,h): 4 gates
__device__ __align__(16) float4 g_b1f4[HH];             // layer1 bias per h
__device__ __align__(16) u32 g_h1f[(size_t)TT * 256 * 3328];  // h1 A-images [t*256+cta][Ah|Al][32][52]
__device__ __align__(16) u64 g_gx[(size_t)TT * BB * HH];      // layer1 gate inputs, 4xfp16 per (t,b,h)
__device__ float g_h2[HH * BB];                         // final h [k][b]

// ---------------- helpers ----------------
// HW tanh (sm_75+): single MUFU op, max abs err ~2e-5 — replaces ex2+rcp chains.
__device__ __forceinline__ float tanh_(float x) {
    float y; asm("tanh.approx.f32 %0, %1;" : "=f"(y) : "f"(x)); return y;
}
__device__ __forceinline__ float sig_(float x) {
    return fmaf(0.5f, tanh_(0.5f * x), 0.5f);
}
static __device__ __forceinline__ u16 f16b(float f) {
    return __half_as_ushort(__float2half_rn(f));
}
static __device__ __forceinline__ float f16f(u16 b) {
    return __half2float(__ushort_as_half(b));
}

#define MMA16(c, a, b0_, b1_) \
    asm volatile("mma.sync.aligned.m16n8k16.row.col.f32.f16.f16.f32 " \
        "{%0,%1,%2,%3},{%4,%5,%6,%7},{%8,%9},{%0,%1,%2,%3};" \
        : "+f"((c)[0]), "+f"((c)[1]), "+f"((c)[2]), "+f"((c)[3]) \
        : "r"((a)[0]), "r"((a)[1]), "r"((a)[2]), "r"((a)[3]), "r"(b0_), "r"(b1_))

#define MMA8(c, a0_, a1_, b0_) \
    asm volatile("mma.sync.aligned.m16n8k8.row.col.f32.f16.f16.f32 " \
        "{%0,%1,%2,%3},{%4,%5},{%6},{%0,%1,%2,%3};" \
        : "+f"((c)[0]), "+f"((c)[1]), "+f"((c)[2]), "+f"((c)[3]) \
        : "r"(a0_), "r"(a1_), "r"(b0_))

// A fragments from a [32 rows][52 k-pairs] u32 pair-image (Ah at 0, Al at +1664)
__device__ __forceinline__ void load_afrags(const u32* Ah, const u32* Al,
                                            int m, int lane, u32 ahi[26], u32 alo[26]) {
    int g = lane >> 2, q = lane & 3;
    int r0 = (m * 16 + g) * 52, r8 = r0 + 8 * 52;
    #pragma unroll
    for (int kt = 0; kt < 6; kt++) {
        int kp = kt * 8 + q;
        ahi[kt * 4 + 0] = Ah[r0 + kp];     ahi[kt * 4 + 1] = Ah[r8 + kp];
        ahi[kt * 4 + 2] = Ah[r0 + kp + 4]; ahi[kt * 4 + 3] = Ah[r8 + kp + 4];
        alo[kt * 4 + 0] = Al[r0 + kp];     alo[kt * 4 + 1] = Al[r8 + kp];
        alo[kt * 4 + 2] = Al[r0 + kp + 4]; alo[kt * 4 + 3] = Al[r8 + kp + 4];
    }
    ahi[24] = Ah[r0 + 48 + q]; ahi[25] = Ah[r8 + 48 + q];
    alo[24] = Al[r0 + 48 + q]; alo[25] = Al[r8 + 48 + q];
}

// One n8 tile x K=104: 2-term fp16 split (Ah*B + Al*B), 2 accumulator chains
__device__ __forceinline__ void mma_tile(float c[4], const u32 ahi[26], const u32 alo[26],
                                         const u32* B, int lane) {
    float cA[4] = {0.f, 0.f, 0.f, 0.f};
    float cB[4] = {0.f, 0.f, 0.f, 0.f};
    #pragma unroll
    for (int kt = 0; kt < 6; kt++) {
        u64 bh = *(const u64*)(B + kt * 64 + lane * 2);
        u32 b0 = (u32)bh, b1 = (u32)(bh >> 32);
        MMA16(cA, ahi + kt * 4, b0, b1);
        MMA16(cB, alo + kt * 4, b0, b1);
    }
    u32 b8 = B[384 + lane];
    MMA8(cA, ahi[24], ahi[25], b8);
    MMA8(cB, alo[24], alo[25], b8);
    #pragma unroll
    for (int i = 0; i < 4; i++) c[i] = cA[i] + cB[i];
}

// ---------------- prep ----------------
__global__ void prep_kernel(const float* __restrict__ embed,
                            const float* __restrict__ Wih0,
                            const float* __restrict__ Whh0,
                            const float* __restrict__ bih0,
                            const float* __restrict__ bhh0,
                            const float* __restrict__ Wih1,
                            const float* __restrict__ Whh1,
                            const float* __restrict__ bih1,
                            const float* __restrict__ bhh1) {
    int stride = gridDim.x * blockDim.x;
    int gid = blockIdx.x * blockDim.x + threadIdx.x;

    // B fragment images (single fp16 term), n' = 4h+gate; j(n') = (n'&3)*100 + (n'>>2)
    for (int idx = gid; idx < 3 * BIMG; idx += stride) {
        int sel = idx / BIMG;
        int r = idx % BIMG;
        const float* W = sel == 0 ? Whh0 : (sel == 1 ? Whh1 : Wih1);
        u32* dst = sel == 0 ? g_Bf_hh0 : (sel == 1 ? g_Bf_hh1 : g_Bf_ih1);
        int nt = r / NTBLK, o = r % NTBLK;
        int lane, kb;
        if (o < 384) {
            int kt = o >> 6; int w = o & 63;
            lane = w >> 1;
            kb = kt * 16 + 2 * (lane & 3) + (w & 1) * 8;
        } else {
            lane = o - 384;
            kb = 96 + 2 * (lane & 3);
        }
        int np = nt * 8 + (lane >> 2);
        int j = (np & 3) * 100 + (np >> 2);
        float w0 = (kb < HH) ? W[j * HH + kb] : 0.f;
        float w1 = (kb + 1 < HH) ? W[j * HH + kb + 1] : 0.f;
        dst[r] = (u32)f16b(w0) | ((u32)f16b(w1) << 16);
    }
    // layer0 table: per (v,h) the 4 gate values of W_ih0*emb[v] + biases
    for (int idx = gid; idx < VV * HH; idx += stride) {
        int v = idx / HH, h = idx % HH;
        float tv[4];
        #pragma unroll
        for (int gt = 0; gt < 4; gt++) {
            int j = gt * HH + h;
            float s = bih0[j] + bhh0[j];
            #pragma unroll
            for (int e = 0; e < 8; e++) s += Wih0[j * 8 + e] * embed[v * 8 + e];
            tv[gt] = s;
        }
        g_tab0[idx] = make_float4(tv[0], tv[1], tv[2], tv[3]);
    }
    // layer1 bias per h
    for (int idx = gid; idx < HH; idx += stride) {
        g_b1f4[idx] = make_float4(bih1[idx] + bhh1[idx],
                                  bih1[HH + idx] + bhh1[HH + idx],
                                  bih1[2 * HH + idx] + bhh1[2 * HH + idx],
                                  bih1[3 * HH + idx] + bhh1[3 * HH + idx]);
    }
}

// ---------------- recurrent layer (L=0: layer0, L=1: layer1) ----------------
// 256 threads, 2 CTAs/SM: warp -> (m = wid&1, nh = wid>>1). 32 batch rows/CTA.
// Ping-pong A buffers -> ONE __syncthreads per step.
template <int L>
__global__ void __launch_bounds__(NTHR, 2) rec_kernel(const int* __restrict__ x) {
    extern __shared__ u32 sm[];
    u32* Bf = sm;

    int tid = threadIdx.x, cta = blockIdx.x;
    int lane = tid & 31, wid = tid >> 5;
    int m = wid & 1, nh = wid >> 1;
    int q = lane & 3;
    int b0 = cta * 32;
    const int base_nt = nh * 13 - (nh == 3 ? 1 : 0);   // 0,13,26,38
    const int cnt = (nh < 2) ? 13 : 12;

    const u32* Bsrc = (L == 0) ? g_Bf_hh0 : g_Bf_hh1;
    for (int i = tid; i < BIMG; i += NTHR) sm[i] = Bsrc[i];
    // Zero BOTH ping-pong buffers: pad columns (hg 100..103) are never written
    // during steps; they must be zero in BOTH buffers or fp16 NaN garbage
    // enters the MMA (NaN * 0 = NaN) — R12 replay-divergence bug.
    for (int i = tid; i < 6656; i += NTHR) sm[A_OFF + i] = 0;
    __syncthreads();

    float cst[13];
    #pragma unroll
    for (int i = 0; i < 13; i++) cst[i] = 0.f;

    int rowA = m * 16 + (lane >> 2) + ((q & 1) ? 8 : 0);
    int bglob = b0 + rowA;
    const int* xrow = x + bglob * TT;

    for (int t = 0; t < TT; t++) {
        int rb = t & 1, wb = rb ^ 1;
        const u32* Ahr = sm + A_OFF + rb * 3328;
        const u32* Alr = Ahr + 1664;
        u16* Ahw = (u16*)(sm + A_OFF + wb * 3328);
        u16* Alw = Ahw + 3328;

        u32 ahi[26], alo[26];
        load_afrags(Ahr, Alr, m, lane, ahi, alo);

        const u64* gxrow = (L == 1) ? (g_gx + ((size_t)t * BB + bglob) * HH) : (const u64*)0;
        int tk = (L == 0) ? xrow[t] : 0;

        #pragma unroll
        for (int ntl = 0; ntl < 13; ntl++) {
            if (ntl >= cnt) break;
            int nta = base_nt + ntl;
            float c[4];
            mma_tile(c, ahi, alo, Bf + nta * NTBLK, lane);

            float s0 = (q & 1) ? c[0] : c[2];
            float s1 = (q & 1) ? c[1] : c[3];
            float x0 = __shfl_xor_sync(0xFFFFFFFFu, s0, 1);
            float x1 = __shfl_xor_sync(0xFFFFFFFFu, s1, 1);
            float gi = (q & 1) ? x0 : c[0];
            float gf = (q & 1) ? x1 : c[1];
            float gg = (q & 1) ? c[2] : x0;
            float go = (q & 1) ? c[3] : x1;

            int hg = nta * 2 + (q >> 1);
            if (L == 0) {
                float4 base = g_tab0[tk * HH + hg];
                gi += base.x; gf += base.y; gg += base.z; go += base.w;
            } else {
                u64 v = gxrow[hg];
                gi += f16f((u16)v);
                gf += f16f((u16)(v >> 16));
                gg += f16f((u16)(v >> 32));
                go += f16f((u16)(v >> 48));
            }

            float iv = sig_(gi), fv = sig_(gf), gv = tanh_(gg), ov = sig_(go);
            float cn = fv * cst[ntl] + iv * gv;
            cst[ntl] = cn;
            float hn = ov * tanh_(cn);

            u16 hb = f16b(hn);
            u16 lb = f16b(hn - f16f(hb));
            Ahw[rowA * 104 + hg] = hb;
            Alw[rowA * 104 + hg] = lb;
            if (L == 1 && t == TT - 1) g_h2[hg * BB + bglob] = hn;
        }
        __syncthreads();   // single per-step sync: orders wb writes before next step's reads

        if (L == 0) {
            uint4* d4 = (uint4*)g_h1f + (size_t)(t * 256 + cta) * 832;
            const uint4* s4 = (const uint4*)(sm + A_OFF + wb * 3328);
            for (int i = tid; i < 832; i += NTHR) d4[i] = s4[i];
        }
    }
}

// ---------------- gx: W_ih1 * h1 + bias for all (t, b) on HMMA --------------
// 256 threads, 2 CTAs/SM, 32-row tiles.
__global__ void __launch_bounds__(NTHR, 2) gx_kernel() {
    extern __shared__ u32 sm[];
    u32* Bf = sm;
    float4* bias = (float4*)(sm + BIAS_OFF);
    u32* Ahs = sm + AGX_OFF;
    u32* Als = Ahs + 1664;

    int tid = threadIdx.x;
    int lane = tid & 31, wid = tid >> 5;
    int m = wid & 1, nh = wid >> 1;
    int q = lane & 3;
    const int base_nt = nh * 13 - (nh == 3 ? 1 : 0);
    const int cnt = (nh < 2) ? 13 : 12;

    for (int i = tid; i < BIMG; i += NTHR) sm[i] = g_Bf_ih1[i];
    for (int i = tid; i < HH; i += NTHR) bias[i] = g_b1f4[i];

    int rowA = m * 16 + (lane >> 2) + ((q & 1) ? 8 : 0);

    for (int tile = blockIdx.x; tile < TT * 256; tile += 296) {
        int t = tile >> 8, bt = tile & 255;
        __syncthreads();
        {
            uint4* d4 = (uint4*)Ahs;
            const uint4* s4 = (const uint4*)(g_h1f + (size_t)tile * 3328);
            for (int i = tid; i < 832; i += NTHR) d4[i] = s4[i];
        }
        __syncthreads();

        u32 ahi[26], alo[26];
        load_afrags(Ahs, Als, m, lane, ahi, alo);

        int bglob = bt * 32 + rowA;
        u64* dst = g_gx + ((size_t)t * BB + bglob) * HH;

        #pragma unroll
        for (int ntl = 0; ntl < 13; ntl++) {
            if (ntl >= cnt) break;
            int nta = base_nt + ntl;
            float c[4];
            mma_tile(c, ahi, alo, Bf + nta * NTBLK, lane);

            float s0 = (q & 1) ? c[0] : c[2];
            float s1 = (q & 1) ? c[1] : c[3];
            float x0 = __shfl_xor_sync(0xFFFFFFFFu, s0, 1);
            float x1 = __shfl_xor_sync(0xFFFFFFFFu, s1, 1);
            float gi = (q & 1) ? x0 : c[0];
            float gf = (q & 1) ? x1 : c[1];
            float gg = (q & 1) ? c[2] : x0;
            float go = (q & 1) ? c[3] : x1;

            int hg = nta * 2 + (q >> 1);
            float4 bv = bias[hg];
            u64 v = (u64)f16b(gi + bv.x)
                  | ((u64)f16b(gf + bv.y) << 16)
                  | ((u64)f16b(gg + bv.z) << 32)
                  | ((u64)f16b(go + bv.w) << 48);
            dst[hg] = v;
        }
    }
}

// ---------------- final FC ----------------
__global__ void __launch_bounds__(256, 1)
fc_kernel(const float* __restrict__ fcW, const float* __restrict__ fcb,
          float* __restrict__ out) {
    __shared__ float Ws[VV * HH];
    __shared__ float bs[VV];
    int tid = threadIdx.x;
    for (int i = tid; i < VV * HH; i += 256) Ws[i] = fcW[i];
    if (tid < VV) bs[tid] = fcb[tid];
    __syncthreads();

    int b = blockIdx.x * 256 + tid;
    float hr[HH];
    #pragma unroll
    for (int k = 0; k < HH; k++) hr[k] = g_h2[k * BB + b];

    const float4* Ws4 = (const float4*)Ws;
    float4* out4 = (float4*)out;
    #pragma unroll 1
    for (int v4 = 0; v4 < 25; v4++) {
        float a[4];
        #pragma unroll
        for (int qq = 0; qq < 4; qq++) a[qq] = bs[v4 * 4 + qq];
        #pragma unroll
        for (int k4 = 0; k4 < 25; k4++) {
            #pragma unroll
            for (int qq = 0; qq < 4; qq++) {
                float4 w = Ws4[(v4 * 4 + qq) * 25 + k4];
                a[qq] += hr[k4 * 4 + 0] * w.x + hr[k4 * 4 + 1] * w.y +
                         hr[k4 * 4 + 2] * w.z + hr[k4 * 4 + 3] * w.w;
            }
        }
        out4[b * 25 + v4] = make_float4(a[0], a[1], a[2], a[3]);
    }
}

// ---------------- launch ----------------
extern "C" void kernel_launch(void* const* d_in, const int* in_sizes, int n_in,
                              void* d_out, int out_size) {
    const int*   x     = (const int*)  d_in[0];
    const float* embed = (const float*)d_in[1];
    const float* Wih0  = (const float*)d_in[2];
    const float* Whh0  = (const float*)d_in[3];
    const float* bih0  = (const float*)d_in[4];
    const float* bhh0  = (const float*)d_in[5];
    const float* Wih1  = (const float*)d_in[6];
    const float* Whh1  = (const float*)d_in[7];
    const float* bih1  = (const float*)d_in[8];
    const float* bhh1  = (const float*)d_in[9];
    const float* fcW   = (const float*)d_in[10];
    const float* fcb   = (const float*)d_in[11];
    float* out = (float*)d_out;

    cudaFuncSetAttribute(rec_kernel<0>, cudaFuncAttributeMaxDynamicSharedMemorySize, SMEM_REC);
    cudaFuncSetAttribute(rec_kernel<1>, cudaFuncAttributeMaxDynamicSharedMemorySize, SMEM_REC);
    cudaFuncSetAttribute(gx_kernel,     cudaFuncAttributeMaxDynamicSharedMemorySize, SMEM_GX);

    prep_kernel<<<160, 256>>>(embed, Wih0, Whh0, bih0, bhh0, Wih1, Whh1, bih1, bhh1);
    rec_kernel<0><<<256, NTHR, SMEM_REC>>>(x);
    gx_kernel<<<296, NTHR, SMEM_GX>>>();
    rec_kernel<1><<<256, NTHR, SMEM_REC>>>(x);
    fc_kernel<<<BB / 256, 256>>>(fcW, fcb, out);
}

// round 16
// speedup vs baseline: 3.6722x; 1.2880x over previous
#include <cuda_runtime.h>
#include <cuda_fp16.h>

typedef unsigned long long u64;
typedef unsigned int u32;
typedef unsigned short u16;

#define BB 8192
#define TT 80
#define HH 100
#define VV 100

#define BIMG  20800           // u32 per single-term B image (50 nt * 416)
#define NTBLK 416             // u32 per n-tile block
#define A_OFF 20800           // rec smem: B | A ping-pong (2 x 1664 u32)
#define SMEM_REC ((20800 + 3328) * 4)
#define BIAS_OFF 20800        // gx smem: B | bias(400) | A(1664)
#define AGX_OFF  21200
#define SMEM_GX ((21200 + 1664) * 4)

#define NTHR 256

// ---------------- device scratch ----------------
__device__ __align__(16) u32 g_Bf_hh0[BIMG];            // W_hh0 fp16 frag image
__device__ __align__(16) u32 g_Bf_hh1[BIMG];            // W_hh1
__device__ __align__(16) u32 g_Bf_ih1[BIMG];            // W_ih1
__device__ __align__(16) float4 g_tab0[VV * HH];        // layer0 table, per (v,h): 4 gates
__device__ __align__(16) float4 g_b1f4[HH];             // layer1 bias per h
__device__ __align__(16) u32 g_h1f[(size_t)TT * 256 * 1664];  // h1 A-images [t*256+cta][32][52]
__device__ __align__(16) u64 g_gx[(size_t)TT * BB * HH];      // layer1 gate inputs, 4xfp16 per (t,b,h)
__device__ float g_h2[HH * BB];                         // final h [k][b]

// ---------------- helpers ----------------
// HW tanh (sm_75+): single MUFU op, max abs err ~2e-5.
__device__ __forceinline__ float tanh_(float x) {
    float y; asm("tanh.approx.f32 %0, %1;" : "=f"(y) : "f"(x)); return y;
}
__device__ __forceinline__ float sig_(float x) {
    return fmaf(0.5f, tanh_(0.5f * x), 0.5f);
}
static __device__ __forceinline__ u16 f16b(float f) {
    return __half_as_ushort(__float2half_rn(f));
}
static __device__ __forceinline__ float f16f(u16 b) {
    return __half2float(__ushort_as_half(b));
}

#define MMA16(c, a, b0_, b1_) \
    asm volatile("mma.sync.aligned.m16n8k16.row.col.f32.f16.f16.f32 " \
        "{%0,%1,%2,%3},{%4,%5,%6,%7},{%8,%9},{%0,%1,%2,%3};" \
        : "+f"((c)[0]), "+f"((c)[1]), "+f"((c)[2]), "+f"((c)[3]) \
        : "r"((a)[0]), "r"((a)[1]), "r"((a)[2]), "r"((a)[3]), "r"(b0_), "r"(b1_))

#define MMA8(c, a0_, a1_, b0_) \
    asm volatile("mma.sync.aligned.m16n8k8.row.col.f32.f16.f16.f32 " \
        "{%0,%1,%2,%3},{%4,%5},{%6},{%0,%1,%2,%3};" \
        : "+f"((c)[0]), "+f"((c)[1]), "+f"((c)[2]), "+f"((c)[3]) \
        : "r"(a0_), "r"(a1_), "r"(b0_))

// A fragments from a [32 rows][52 k-pairs] u32 image (single fp16 term)
__device__ __forceinline__ void load_afrags(const u32* Ah, int m, int lane, u32 ahi[26]) {
    int g = lane >> 2, q = lane & 3;
    int r0 = (m * 16 + g) * 52, r8 = r0 + 8 * 52;
    #pragma unroll
    for (int kt = 0; kt < 6; kt++) {
        int kp = kt * 8 + q;
        ahi[kt * 4 + 0] = Ah[r0 + kp];     ahi[kt * 4 + 1] = Ah[r8 + kp];
        ahi[kt * 4 + 2] = Ah[r0 + kp + 4]; ahi[kt * 4 + 3] = Ah[r8 + kp + 4];
    }
    ahi[24] = Ah[r0 + 48 + q]; ahi[25] = Ah[r8 + 48 + q];
}

// One n8 tile x K=104, single fp16 term, 2 accumulator chains for ILP
__device__ __forceinline__ void mma_tile(float c[4], const u32 ahi[26],
                                         const u32* B, int lane) {
    float cA[4] = {0.f, 0.f, 0.f, 0.f};
    float cB[4] = {0.f, 0.f, 0.f, 0.f};
    #pragma unroll
    for (int kt = 0; kt < 6; kt++) {
        u64 bh = *(const u64*)(B + kt * 64 + lane * 2);
        u32 b0 = (u32)bh, b1 = (u32)(bh >> 32);
        if (kt < 3) { MMA16(cA, ahi + kt * 4, b0, b1); }
        else        { MMA16(cB, ahi + kt * 4, b0, b1); }
    }
    u32 b8 = B[384 + lane];
    MMA8(cA, ahi[24], ahi[25], b8);
    #pragma unroll
    for (int i = 0; i < 4; i++) c[i] = cA[i] + cB[i];
}

// ---------------- prep ----------------
__global__ void prep_kernel(const float* __restrict__ embed,
                            const float* __restrict__ Wih0,
                            const float* __restrict__ Whh0,
                            const float* __restrict__ bih0,
                            const float* __restrict__ bhh0,
                            const float* __restrict__ Wih1,
                            const float* __restrict__ Whh1,
                            const float* __restrict__ bih1,
                            const float* __restrict__ bhh1) {
    int stride = gridDim.x * blockDim.x;
    int gid = blockIdx.x * blockDim.x + threadIdx.x;

    // B fragment images (single fp16 term), n' = 4h+gate; j(n') = (n'&3)*100 + (n'>>2)
    for (int idx = gid; idx < 3 * BIMG; idx += stride) {
        int sel = idx / BIMG;
        int r = idx % BIMG;
        const float* W = sel == 0 ? Whh0 : (sel == 1 ? Whh1 : Wih1);
        u32* dst = sel == 0 ? g_Bf_hh0 : (sel == 1 ? g_Bf_hh1 : g_Bf_ih1);
        int nt = r / NTBLK, o = r % NTBLK;
        int lane, kb;
        if (o < 384) {
            int kt = o >> 6; int w = o & 63;
            lane = w >> 1;
            kb = kt * 16 + 2 * (lane & 3) + (w & 1) * 8;
        } else {
            lane = o - 384;
            kb = 96 + 2 * (lane & 3);
        }
        int np = nt * 8 + (lane >> 2);
        int j = (np & 3) * 100 + (np >> 2);
        float w0 = (kb < HH) ? W[j * HH + kb] : 0.f;
        float w1 = (kb + 1 < HH) ? W[j * HH + kb + 1] : 0.f;
        dst[r] = (u32)f16b(w0) | ((u32)f16b(w1) << 16);
    }
    // layer0 table: per (v,h) the 4 gate values of W_ih0*emb[v] + biases
    for (int idx = gid; idx < VV * HH; idx += stride) {
        int v = idx / HH, h = idx % HH;
        float tv[4];
        #pragma unroll
        for (int gt = 0; gt < 4; gt++) {
            int j = gt * HH + h;
            float s = bih0[j] + bhh0[j];
            #pragma unroll
            for (int e = 0; e < 8; e++) s += Wih0[j * 8 + e] * embed[v * 8 + e];
            tv[gt] = s;
        }
        g_tab0[idx] = make_float4(tv[0], tv[1], tv[2], tv[3]);
    }
    // layer1 bias per h
    for (int idx = gid; idx < HH; idx += stride) {
        g_b1f4[idx] = make_float4(bih1[idx] + bhh1[idx],
                                  bih1[HH + idx] + bhh1[HH + idx],
                                  bih1[2 * HH + idx] + bhh1[2 * HH + idx],
                                  bih1[3 * HH + idx] + bhh1[3 * HH + idx]);
    }
}

// ---------------- recurrent layer (L=0: layer0, L=1: layer1) ----------------
// 256 threads, 2 CTAs/SM: warp -> (m = wid&1, nh = wid>>1). 32 batch rows/CTA.
// Ping-pong A buffers (1664 u32 each) -> ONE __syncthreads per step.
template <int L>
__global__ void __launch_bounds__(NTHR, 2) rec_kernel(const int* __restrict__ x) {
    extern __shared__ u32 sm[];
    u32* Bf = sm;

    int tid = threadIdx.x, cta = blockIdx.x;
    int lane = tid & 31, wid = tid >> 5;
    int m = wid & 1, nh = wid >> 1;
    int q = lane & 3;
    int b0 = cta * 32;
    const int base_nt = nh * 13 - (nh == 3 ? 1 : 0);   // 0,13,26,38
    const int cnt = (nh < 2) ? 13 : 12;

    const u32* Bsrc = (L == 0) ? g_Bf_hh0 : g_Bf_hh1;
    for (int i = tid; i < BIMG; i += NTHR) sm[i] = Bsrc[i];
    // Zero BOTH ping-pong buffers (pad columns hg 100..103 must stay zero in
    // both buffers forever — fp16 NaN garbage enters the MMA otherwise).
    for (int i = tid; i < 3328; i += NTHR) sm[A_OFF + i] = 0;
    __syncthreads();

    float cst[13];
    #pragma unroll
    for (int i = 0; i < 13; i++) cst[i] = 0.f;

    int rowA = m * 16 + (lane >> 2) + ((q & 1) ? 8 : 0);
    int bglob = b0 + rowA;
    const int* xrow = x + bglob * TT;

    for (int t = 0; t < TT; t++) {
        int rb = t & 1, wb = rb ^ 1;
        const u32* Ahr = sm + A_OFF + rb * 1664;
        u16* Ahw = (u16*)(sm + A_OFF + wb * 1664);

        u32 ahi[26];
        load_afrags(Ahr, m, lane, ahi);

        const u64* gxrow = (L == 1) ? (g_gx + ((size_t)t * BB + bglob) * HH) : (const u64*)0;
        int tk = (L == 0) ? xrow[t] : 0;

        #pragma unroll
        for (int ntl = 0; ntl < 13; ntl++) {
            if (ntl >= cnt) break;
            int nta = base_nt + ntl;
            float c[4];
            mma_tile(c, ahi, Bf + nta * NTBLK, lane);

            float s0 = (q & 1) ? c[0] : c[2];
            float s1 = (q & 1) ? c[1] : c[3];
            float x0 = __shfl_xor_sync(0xFFFFFFFFu, s0, 1);
            float x1 = __shfl_xor_sync(0xFFFFFFFFu, s1, 1);
            float gi = (q & 1) ? x0 : c[0];
            float gf = (q & 1) ? x1 : c[1];
            float gg = (q & 1) ? c[2] : x0;
            float go = (q & 1) ? c[3] : x1;

            int hg = nta * 2 + (q >> 1);
            if (L == 0) {
                float4 base = g_tab0[tk * HH + hg];
                gi += base.x; gf += base.y; gg += base.z; go += base.w;
            } else {
                u64 v = gxrow[hg];
                gi += f16f((u16)v);
                gf += f16f((u16)(v >> 16));
                gg += f16f((u16)(v >> 32));
                go += f16f((u16)(v >> 48));
            }

            float iv = sig_(gi), fv = sig_(gf), gv = tanh_(gg), ov = sig_(go);
            float cn = fv * cst[ntl] + iv * gv;
            cst[ntl] = cn;
            float hn = ov * tanh_(cn);

            Ahw[rowA * 104 + hg] = f16b(hn);
            if (L == 1 && t == TT - 1) g_h2[hg * BB + bglob] = hn;
        }
        __syncthreads();   // single per-step sync: orders wb writes before next step's reads

        if (L == 0) {
            uint4* d4 = (uint4*)g_h1f + (size_t)(t * 256 + cta) * 416;
            const uint4* s4 = (const uint4*)(sm + A_OFF + wb * 1664);
            for (int i = tid; i < 416; i += NTHR) d4[i] = s4[i];
        }
    }
}

// ---------------- gx: W_ih1 * h1 + bias for all (t, b) on HMMA --------------
// 256 threads, 2 CTAs/SM, 32-row tiles.
__global__ void __launch_bounds__(NTHR, 2) gx_kernel() {
    extern __shared__ u32 sm[];
    u32* Bf = sm;
    float4* bias = (float4*)(sm + BIAS_OFF);
    u32* Ahs = sm + AGX_OFF;

    int tid = threadIdx.x;
    int lane = tid & 31, wid = tid >> 5;
    int m = wid & 1, nh = wid >> 1;
    int q = lane & 3;
    const int base_nt = nh * 13 - (nh == 3 ? 1 : 0);
    const int cnt = (nh < 2) ? 13 : 12;

    for (int i = tid; i < BIMG; i += NTHR) sm[i] = g_Bf_ih1[i];
    for (int i = tid; i < HH; i += NTHR) bias[i] = g_b1f4[i];

    int rowA = m * 16 + (lane >> 2) + ((q & 1) ? 8 : 0);

    for (int tile = blockIdx.x; tile < TT * 256; tile += 296) {
        int t = tile >> 8, bt = tile & 255;
        __syncthreads();
        {
            uint4* d4 = (uint4*)Ahs;
            const uint4* s4 = (const uint4*)g_h1f + (size_t)tile * 416;
            for (int i = tid; i < 416; i += NTHR) d4[i] = s4[i];
        }
        __syncthreads();

        u32 ahi[26];
        load_afrags(Ahs, m, lane, ahi);

        int bglob = bt * 32 + rowA;
        u64* dst = g_gx + ((size_t)t * BB + bglob) * HH;

        #pragma unroll
        for (int ntl = 0; ntl < 13; ntl++) {
            if (ntl >= cnt) break;
            int nta = base_nt + ntl;
            float c[4];
            mma_tile(c, ahi, Bf + nta * NTBLK, lane);

            float s0 = (q & 1) ? c[0] : c[2];
            float s1 = (q & 1) ? c[1] : c[3];
            float x0 = __shfl_xor_sync(0xFFFFFFFFu, s0, 1);
            float x1 = __shfl_xor_sync(0xFFFFFFFFu, s1, 1);
            float gi = (q & 1) ? x0 : c[0];
            float gf = (q & 1) ? x1 : c[1];
            float gg = (q & 1) ? c[2] : x0;
            float go = (q & 1) ? c[3] : x1;

            int hg = nta * 2 + (q >> 1);
            float4 bv = bias[hg];
            u64 v = (u64)f16b(gi + bv.x)
                  | ((u64)f16b(gf + bv.y) << 16)
                  | ((u64)f16b(gg + bv.z) << 32)
                  | ((u64)f16b(go + bv.w) << 48);
            dst[hg] = v;
        }
    }
}

// ---------------- final FC ----------------
__global__ void __launch_bounds__(256, 1)
fc_kernel(const float* __restrict__ fcW, const float* __restrict__ fcb,
          float* __restrict__ out) {
    __shared__ float Ws[VV * HH];
    __shared__ float bs[VV];
    int tid = threadIdx.x;
    for (int i = tid; i < VV * HH; i += 256) Ws[i] = fcW[i];
    if (tid < VV) bs[tid] = fcb[tid];
    __syncthreads();

    int b = blockIdx.x * 256 + tid;
    float hr[HH];
    #pragma unroll
    for (int k = 0; k < HH; k++) hr[k] = g_h2[k * BB + b];

    const float4* Ws4 = (const float4*)Ws;
    float4* out4 = (float4*)out;
    #pragma unroll 1
    for (int v4 = 0; v4 < 25; v4++) {
        float a[4];
        #pragma unroll
        for (int qq = 0; qq < 4; qq++) a[qq] = bs[v4 * 4 + qq];
        #pragma unroll
        for (int k4 = 0; k4 < 25; k4++) {
            #pragma unroll
            for (int qq = 0; qq < 4; qq++) {
                float4 w = Ws4[(v4 * 4 + qq) * 25 + k4];
                a[qq] += hr[k4 * 4 + 0] * w.x + hr[k4 * 4 + 1] * w.y +
                         hr[k4 * 4 + 2] * w.z + hr[k4 * 4 + 3] * w.w;
            }
        }
        out4[b * 25 + v4] = make_float4(a[0], a[1], a[2], a[3]);
    }
}

// ---------------- launch ----------------
extern "C" void kernel_launch(void* const* d_in, const int* in_sizes, int n_in,
                              void* d_out, int out_size) {
    const int*   x     = (const int*)  d_in[0];
    const float* embed = (const float*)d_in[1];
    const float* Wih0  = (const float*)d_in[2];
    const float* Whh0  = (const float*)d_in[3];
    const float* bih0  = (const float*)d_in[4];
    const float* bhh0  = (const float*)d_in[5];
    const float* Wih1  = (const float*)d_in[6];
    const float* Whh1  = (const float*)d_in[7];
    const float* bih1  = (const float*)d_in[8];
    const float* bhh1  = (const float*)d_in[9];
    const float* fcW   = (const float*)d_in[10];
    const float* fcb   = (const float*)d_in[11];
    float* out = (float*)d_out;

    cudaFuncSetAttribute(rec_kernel<0>, cudaFuncAttributeMaxDynamicSharedMemorySize, SMEM_REC);
    cudaFuncSetAttribute(rec_kernel<1>, cudaFuncAttributeMaxDynamicSharedMemorySize, SMEM_REC);
    cudaFuncSetAttribute(gx_kernel,     cudaFuncAttributeMaxDynamicSharedMemorySize, SMEM_GX);

    prep_kernel<<<160, 256>>>(embed, Wih0, Whh0, bih0, bhh0, Wih1, Whh1, bih1, bhh1);
    rec_kernel<0><<<256, NTHR, SMEM_REC>>>(x);
    gx_kernel<<<296, NTHR, SMEM_GX>>>();
    rec_kernel<1><<<256, NTHR, SMEM_REC>>>(x);
    fc_kernel<<<BB / 256, 256>>>(fcW, fcb, out);
}

// round 17
// speedup vs baseline: 4.2766x; 1.1646x over previous
#include <cuda_runtime.h>
#include <cuda_fp16.h>

typedef unsigned long long u64;
typedef unsigned int u32;
typedef unsigned short u16;

#define BB 8192
#define TT 80
#define HH 100
#define VV 100

#define BIMG  20800           // u32 per single-term B image (50 nt * 416)
#define NTBLK 416             // u32 per n-tile block
#define A_OFF 20800           // rec smem: B | A ping-pong (2 x 1664 u32)
#define SMEM_REC ((20800 + 3328) * 4)
#define BIAS_OFF 20800        // gx smem: B | bias(400) | A(1664)
#define AGX_OFF  21200
#define SMEM_GX ((21200 + 1664) * 4)

#define NTHR 256

// ---------------- device scratch ----------------
__device__ __align__(16) u32 g_Bf_hh0[BIMG];            // W_hh0 fp16 frag image
__device__ __align__(16) u32 g_Bf_hh1[BIMG];            // W_hh1
__device__ __align__(16) u32 g_Bf_ih1[BIMG];            // W_ih1
__device__ __align__(16) float4 g_tab0[VV * HH];        // layer0 table, per (v,h): 4 gates
__device__ __align__(16) float4 g_b1f4[HH];             // layer1 bias per h
__device__ __align__(16) u32 g_h1f[(size_t)TT * 256 * 1664];  // h1 A-images [t*256+cta][32][52]
__device__ __align__(16) u64 g_gx[(size_t)TT * BB * HH];      // layer1 gate inputs, 4xfp16 per (t,b,h)
__device__ float g_h2[HH * BB];                         // final h [k][b]

// ---------------- helpers ----------------
__device__ __forceinline__ float tanh_(float x) {
    float y; asm("tanh.approx.f32 %0, %1;" : "=f"(y) : "f"(x)); return y;
}
__device__ __forceinline__ float sig_(float x) {
    return fmaf(0.5f, tanh_(0.5f * x), 0.5f);
}
static __device__ __forceinline__ u16 f16b(float f) {
    return __half_as_ushort(__float2half_rn(f));
}
static __device__ __forceinline__ float f16f(u16 b) {
    return __half2float(__ushort_as_half(b));
}

#define MMA16(c, a, b0_, b1_) \
    asm volatile("mma.sync.aligned.m16n8k16.row.col.f32.f16.f16.f32 " \
        "{%0,%1,%2,%3},{%4,%5,%6,%7},{%8,%9},{%0,%1,%2,%3};" \
        : "+f"((c)[0]), "+f"((c)[1]), "+f"((c)[2]), "+f"((c)[3]) \
        : "r"((a)[0]), "r"((a)[1]), "r"((a)[2]), "r"((a)[3]), "r"(b0_), "r"(b1_))

#define MMA8(c, a0_, a1_, b0_) \
    asm volatile("mma.sync.aligned.m16n8k8.row.col.f32.f16.f16.f32 " \
        "{%0,%1,%2,%3},{%4,%5},{%6},{%0,%1,%2,%3};" \
        : "+f"((c)[0]), "+f"((c)[1]), "+f"((c)[2]), "+f"((c)[3]) \
        : "r"(a0_), "r"(a1_), "r"(b0_))

// A fragments for m-tile m from a [32 rows][52 k-pairs] u32 image
__device__ __forceinline__ void load_afrags(const u32* Ah, int m, int lane, u32 ahi[26]) {
    int g = lane >> 2, q = lane & 3;
    int r0 = (m * 16 + g) * 52, r8 = r0 + 8 * 52;
    #pragma unroll
    for (int kt = 0; kt < 6; kt++) {
        int kp = kt * 8 + q;
        ahi[kt * 4 + 0] = Ah[r0 + kp];     ahi[kt * 4 + 1] = Ah[r8 + kp];
        ahi[kt * 4 + 2] = Ah[r0 + kp + 4]; ahi[kt * 4 + 3] = Ah[r8 + kp + 4];
    }
    ahi[24] = Ah[r0 + 48 + q]; ahi[25] = Ah[r8 + 48 + q];
}

// One n8 tile x K=104 for BOTH m-tiles: B loaded ONCE, reused for 2 MMA chains.
__device__ __forceinline__ void mma_tile2(float c0[4], float c1[4],
                                          const u32 a0[26], const u32 a1[26],
                                          const u32* B, int lane) {
    u32 br[13];
    #pragma unroll
    for (int kt = 0; kt < 6; kt++) {
        u64 bh = *(const u64*)(B + kt * 64 + lane * 2);
        br[2 * kt] = (u32)bh; br[2 * kt + 1] = (u32)(bh >> 32);
    }
    br[12] = B[384 + lane];
    float cA[4] = {0.f, 0.f, 0.f, 0.f};
    float cB[4] = {0.f, 0.f, 0.f, 0.f};
    float cC[4] = {0.f, 0.f, 0.f, 0.f};
    float cD[4] = {0.f, 0.f, 0.f, 0.f};
    #pragma unroll
    for (int kt = 0; kt < 6; kt++) {
        if (kt < 3) {
            MMA16(cA, a0 + kt * 4, br[2 * kt], br[2 * kt + 1]);
            MMA16(cC, a1 + kt * 4, br[2 * kt], br[2 * kt + 1]);
        } else {
            MMA16(cB, a0 + kt * 4, br[2 * kt], br[2 * kt + 1]);
            MMA16(cD, a1 + kt * 4, br[2 * kt], br[2 * kt + 1]);
        }
    }
    MMA8(cA, a0[24], a0[25], br[12]);
    MMA8(cC, a1[24], a1[25], br[12]);
    #pragma unroll
    for (int i = 0; i < 4; i++) { c0[i] = cA[i] + cB[i]; c1[i] = cC[i] + cD[i]; }
}

// gate exchange + LSTM cell for one (row, n-tile) pair
__device__ __forceinline__ float cell_from_c(const float c[4], int q, float base_i,
                                             float base_f, float base_g, float base_o,
                                             float& cstate) {
    float s0 = (q & 1) ? c[0] : c[2];
    float s1 = (q & 1) ? c[1] : c[3];
    float x0 = __shfl_xor_sync(0xFFFFFFFFu, s0, 1);
    float x1 = __shfl_xor_sync(0xFFFFFFFFu, s1, 1);
    float gi = ((q & 1) ? x0 : c[0]) + base_i;
    float gf = ((q & 1) ? x1 : c[1]) + base_f;
    float gg = ((q & 1) ? c[2] : x0) + base_g;
    float go = ((q & 1) ? c[3] : x1) + base_o;
    float iv = sig_(gi), fv = sig_(gf), gv = tanh_(gg), ov = sig_(go);
    float cn = fv * cstate + iv * gv;
    cstate = cn;
    return ov * tanh_(cn);
}

// ---------------- prep ----------------
__global__ void prep_kernel(const float* __restrict__ embed,
                            const float* __restrict__ Wih0,
                            const float* __restrict__ Whh0,
                            const float* __restrict__ bih0,
                            const float* __restrict__ bhh0,
                            const float* __restrict__ Wih1,
                            const float* __restrict__ Whh1,
                            const float* __restrict__ bih1,
                            const float* __restrict__ bhh1) {
    int stride = gridDim.x * blockDim.x;
    int gid = blockIdx.x * blockDim.x + threadIdx.x;

    for (int idx = gid; idx < 3 * BIMG; idx += stride) {
        int sel = idx / BIMG;
        int r = idx % BIMG;
        const float* W = sel == 0 ? Whh0 : (sel == 1 ? Whh1 : Wih1);
        u32* dst = sel == 0 ? g_Bf_hh0 : (sel == 1 ? g_Bf_hh1 : g_Bf_ih1);
        int nt = r / NTBLK, o = r % NTBLK;
        int lane, kb;
        if (o < 384) {
            int kt = o >> 6; int w = o & 63;
            lane = w >> 1;
            kb = kt * 16 + 2 * (lane & 3) + (w & 1) * 8;
        } else {
            lane = o - 384;
            kb = 96 + 2 * (lane & 3);
        }
        int np = nt * 8 + (lane >> 2);
        int j = (np & 3) * 100 + (np >> 2);
        float w0 = (kb < HH) ? W[j * HH + kb] : 0.f;
        float w1 = (kb + 1 < HH) ? W[j * HH + kb + 1] : 0.f;
        dst[r] = (u32)f16b(w0) | ((u32)f16b(w1) << 16);
    }
    for (int idx = gid; idx < VV * HH; idx += stride) {
        int v = idx / HH, h = idx % HH;
        float tv[4];
        #pragma unroll
        for (int gt = 0; gt < 4; gt++) {
            int j = gt * HH + h;
            float s = bih0[j] + bhh0[j];
            #pragma unroll
            for (int e = 0; e < 8; e++) s += Wih0[j * 8 + e] * embed[v * 8 + e];
            tv[gt] = s;
        }
        g_tab0[idx] = make_float4(tv[0], tv[1], tv[2], tv[3]);
    }
    for (int idx = gid; idx < HH; idx += stride) {
        g_b1f4[idx] = make_float4(bih1[idx] + bhh1[idx],
                                  bih1[HH + idx] + bhh1[HH + idx],
                                  bih1[2 * HH + idx] + bhh1[2 * HH + idx],
                                  bih1[3 * HH + idx] + bhh1[3 * HH + idx]);
    }
}

// ---------------- recurrent layer (L=0: layer0, L=1: layer1) ----------------
// 256 threads, 2 CTAs/SM. Warp owns BOTH m-tiles for its n-tile group
// (50 tiles split 6,6,6,6,6,6,7,7) — B fragments loaded once, used twice.
template <int L>
__global__ void __launch_bounds__(NTHR, 2) rec_kernel(const int* __restrict__ x) {
    extern __shared__ u32 sm[];
    u32* Bf = sm;

    int tid = threadIdx.x, cta = blockIdx.x;
    int lane = tid & 31, wid = tid >> 5;
    int q = lane & 3;
    int b0 = cta * 32;
    const int base_nt = wid * 6 + (wid == 7 ? 1 : 0);
    const int cnt = (wid < 6) ? 6 : 7;

    const u32* Bsrc = (L == 0) ? g_Bf_hh0 : g_Bf_hh1;
    for (int i = tid; i < BIMG; i += NTHR) sm[i] = Bsrc[i];
    // Zero BOTH ping-pong buffers (pad columns hg 100..103 must stay zero in
    // both buffers forever — fp16 NaN garbage enters the MMA otherwise).
    for (int i = tid; i < 3328; i += NTHR) sm[A_OFF + i] = 0;
    __syncthreads();

    float cst[2][7];
    #pragma unroll
    for (int mm = 0; mm < 2; mm++)
        #pragma unroll
        for (int i = 0; i < 7; i++) cst[mm][i] = 0.f;

    int rowA0 = (lane >> 2) + ((q & 1) ? 8 : 0);
    int rowA1 = rowA0 + 16;
    int bg0 = b0 + rowA0, bg1 = b0 + rowA1;
    const int* xr0 = x + bg0 * TT;
    const int* xr1 = x + bg1 * TT;

    for (int t = 0; t < TT; t++) {
        int rb = t & 1, wb = rb ^ 1;
        const u32* Ahr = sm + A_OFF + rb * 1664;
        u16* Ahw = (u16*)(sm + A_OFF + wb * 1664);

        u32 a0[26], a1[26];
        load_afrags(Ahr, 0, lane, a0);
        load_afrags(Ahr, 1, lane, a1);

        const u64* gxr0 = (L == 1) ? (g_gx + ((size_t)t * BB + bg0) * HH) : (const u64*)0;
        const u64* gxr1 = (L == 1) ? (g_gx + ((size_t)t * BB + bg1) * HH) : (const u64*)0;
        int tk0 = (L == 0) ? xr0[t] : 0;
        int tk1 = (L == 0) ? xr1[t] : 0;

        #pragma unroll
        for (int ntl = 0; ntl < 7; ntl++) {
            if (ntl >= cnt) break;
            int nta = base_nt + ntl;
            float c0[4], c1[4];
            mma_tile2(c0, c1, a0, a1, Bf + nta * NTBLK, lane);

            int hg = nta * 2 + (q >> 1);
            float bi0, bf0, bg0v, bo0, bi1, bf1, bg1v, bo1;
            if (L == 0) {
                float4 t0 = g_tab0[tk0 * HH + hg];
                float4 t1 = g_tab0[tk1 * HH + hg];
                bi0 = t0.x; bf0 = t0.y; bg0v = t0.z; bo0 = t0.w;
                bi1 = t1.x; bf1 = t1.y; bg1v = t1.z; bo1 = t1.w;
            } else {
                u64 v0 = gxr0[hg], v1 = gxr1[hg];
                bi0 = f16f((u16)v0); bf0 = f16f((u16)(v0 >> 16));
                bg0v = f16f((u16)(v0 >> 32)); bo0 = f16f((u16)(v0 >> 48));
                bi1 = f16f((u16)v1); bf1 = f16f((u16)(v1 >> 16));
                bg1v = f16f((u16)(v1 >> 32)); bo1 = f16f((u16)(v1 >> 48));
            }

            float hn0 = cell_from_c(c0, q, bi0, bf0, bg0v, bo0, cst[0][ntl]);
            float hn1 = cell_from_c(c1, q, bi1, bf1, bg1v, bo1, cst[1][ntl]);

            Ahw[rowA0 * 104 + hg] = f16b(hn0);
            Ahw[rowA1 * 104 + hg] = f16b(hn1);
            if (L == 1 && t == TT - 1) {
                g_h2[hg * BB + bg0] = hn0;
                g_h2[hg * BB + bg1] = hn1;
            }
        }
        __syncthreads();   // single per-step sync

        if (L == 0) {
            uint4* d4 = (uint4*)g_h1f + (size_t)(t * 256 + cta) * 416;
            const uint4* s4 = (const uint4*)(sm + A_OFF + wb * 1664);
            for (int i = tid; i < 416; i += NTHR) d4[i] = s4[i];
        }
    }
}

// ---------------- gx: W_ih1 * h1 + bias for all (t, b) on HMMA --------------
__global__ void __launch_bounds__(NTHR, 2) gx_kernel() {
    extern __shared__ u32 sm[];
    u32* Bf = sm;
    float4* bias = (float4*)(sm + BIAS_OFF);
    u32* Ahs = sm + AGX_OFF;

    int tid = threadIdx.x;
    int lane = tid & 31, wid = tid >> 5;
    int q = lane & 3;
    const int base_nt = wid * 6 + (wid == 7 ? 1 : 0);
    const int cnt = (wid < 6) ? 6 : 7;

    for (int i = tid; i < BIMG; i += NTHR) sm[i] = g_Bf_ih1[i];
    for (int i = tid; i < HH; i += NTHR) bias[i] = g_b1f4[i];

    int rowA0 = (lane >> 2) + ((q & 1) ? 8 : 0);
    int rowA1 = rowA0 + 16;

    for (int tile = blockIdx.x; tile < TT * 256; tile += 296) {
        int t = tile >> 8, bt = tile & 255;
        __syncthreads();
        {
            uint4* d4 = (uint4*)Ahs;
            const uint4* s4 = (const uint4*)g_h1f + (size_t)tile * 416;
            for (int i = tid; i < 416; i += NTHR) d4[i] = s4[i];
        }
        __syncthreads();

        u32 a0[26], a1[26];
        load_afrags(Ahs, 0, lane, a0);
        load_afrags(Ahs, 1, lane, a1);

        int bg0 = bt * 32 + rowA0, bg1 = bt * 32 + rowA1;
        u64* dst0 = g_gx + ((size_t)t * BB + bg0) * HH;
        u64* dst1 = g_gx + ((size_t)t * BB + bg1) * HH;

        #pragma unroll
        for (int ntl = 0; ntl < 7; ntl++) {
            if (ntl >= cnt) break;
            int nta = base_nt + ntl;
            float c0[4], c1[4];
            mma_tile2(c0, c1, a0, a1, Bf + nta * NTBLK, lane);

            int hg = nta * 2 + (q >> 1);
            float4 bv = bias[hg];
            {
                float s0 = (q & 1) ? c0[0] : c0[2];
                float s1 = (q & 1) ? c0[1] : c0[3];
                float x0 = __shfl_xor_sync(0xFFFFFFFFu, s0, 1);
                float x1 = __shfl_xor_sync(0xFFFFFFFFu, s1, 1);
                float gi = ((q & 1) ? x0 : c0[0]) + bv.x;
                float gf = ((q & 1) ? x1 : c0[1]) + bv.y;
                float gg = ((q & 1) ? c0[2] : x0) + bv.z;
                float go = ((q & 1) ? c0[3] : x1) + bv.w;
                dst0[hg] = (u64)f16b(gi) | ((u64)f16b(gf) << 16)
                         | ((u64)f16b(gg) << 32) | ((u64)f16b(go) << 48);
            }
            {
                float s0 = (q & 1) ? c1[0] : c1[2];
                float s1 = (q & 1) ? c1[1] : c1[3];
                float x0 = __shfl_xor_sync(0xFFFFFFFFu, s0, 1);
                float x1 = __shfl_xor_sync(0xFFFFFFFFu, s1, 1);
                float gi = ((q & 1) ? x0 : c1[0]) + bv.x;
                float gf = ((q & 1) ? x1 : c1[1]) + bv.y;
                float gg = ((q & 1) ? c1[2] : x0) + bv.z;
                float go = ((q & 1) ? c1[3] : x1) + bv.w;
                dst1[hg] = (u64)f16b(gi) | ((u64)f16b(gf) << 16)
                         | ((u64)f16b(gg) << 32) | ((u64)f16b(go) << 48);
            }
        }
    }
}

// ---------------- final FC ----------------
__global__ void __launch_bounds__(256, 1)
fc_kernel(const float* __restrict__ fcW, const float* __restrict__ fcb,
          float* __restrict__ out) {
    __shared__ float Ws[VV * HH];
    __shared__ float bs[VV];
    int tid = threadIdx.x;
    for (int i = tid; i < VV * HH; i += 256) Ws[i] = fcW[i];
    if (tid < VV) bs[tid] = fcb[tid];
    __syncthreads();

    int b = blockIdx.x * 256 + tid;
    float hr[HH];
    #pragma unroll
    for (int k = 0; k < HH; k++) hr[k] = g_h2[k * BB + b];

    const float4* Ws4 = (const float4*)Ws;
    float4* out4 = (float4*)out;
    #pragma unroll 1
    for (int v4 = 0; v4 < 25; v4++) {
        float a[4];
        #pragma unroll
        for (int qq = 0; qq < 4; qq++) a[qq] = bs[v4 * 4 + qq];
        #pragma unroll
        for (int k4 = 0; k4 < 25; k4++) {
            #pragma unroll
            for (int qq = 0; qq < 4; qq++) {
                float4 w = Ws4[(v4 * 4 + qq) * 25 + k4];
                a[qq] += hr[k4 * 4 + 0] * w.x + hr[k4 * 4 + 1] * w.y +
                         hr[k4 * 4 + 2] * w.z + hr[k4 * 4 + 3] * w.w;
            }
        }
        out4[b * 25 + v4] = make_float4(a[0], a[1], a[2], a[3]);
    }
}

// ---------------- launch ----------------
extern "C" void kernel_launch(void* const* d_in, const int* in_sizes, int n_in,
                              void* d_out, int out_size) {
    const int*   x     = (const int*)  d_in[0];
    const float* embed = (const float*)d_in[1];
    const float* Wih0  = (const float*)d_in[2];
    const float* Whh0  = (const float*)d_in[3];
    const float* bih0  = (const float*)d_in[4];
    const float* bhh0  = (const float*)d_in[5];
    const float* Wih1  = (const float*)d_in[6];
    const float* Whh1  = (const float*)d_in[7];
    const float* bih1  = (const float*)d_in[8];
    const float* bhh1  = (const float*)d_in[9];
    const float* fcW   = (const float*)d_in[10];
    const float* fcb   = (const float*)d_in[11];
    float* out = (float*)d_out;

    cudaFuncSetAttribute(rec_kernel<0>, cudaFuncAttributeMaxDynamicSharedMemorySize, SMEM_REC);
    cudaFuncSetAttribute(rec_kernel<1>, cudaFuncAttributeMaxDynamicSharedMemorySize, SMEM_REC);
    cudaFuncSetAttribute(gx_kernel,     cudaFuncAttributeMaxDynamicSharedMemorySize, SMEM_GX);

    prep_kernel<<<160, 256>>>(embed, Wih0, Whh0, bih0, bhh0, Wih1, Whh1, bih1, bhh1);
    rec_kernel<0><<<256, NTHR, SMEM_REC>>>(x);
    gx_kernel<<<296, NTHR, SMEM_GX>>>();
    rec_kernel<1><<<256, NTHR, SMEM_REC>>>(x);
    fc_kernel<<<BB / 256, 256>>>(fcW, fcb, out);
}